// round 3
// baseline (speedup 1.0000x reference)
#include <cuda_runtime.h>
#include <math.h>

#define NN 100000
#define DD 128
#define KE 16
#define NB 782            // ceil(NN/128)
#define DTS 0.1f
#define SP 132            // padded row stride (floats) for 128-wide tiles
#define UP 17             // padded row stride for U tile

// Scratch state (no allocations allowed) — ~109 MB total
__device__ float g_Y[NN * DD];        // current RK4 evaluation point
__device__ float g_acc[NN * DD];      // k1 + 2k2 + 2k3 accumulator
__device__ float g_part[NB * KE * DD];// per-block partial U^T Y
__device__ float g_G[KE * DD];        // reduced G = U^T Y

__device__ __forceinline__ float sigm(float x) { return 1.0f / (1.0f + __expf(-x)); }

// ---------------------------------------------------------------------------
// init: H (d_out) = Y = h0
// ---------------------------------------------------------------------------
__global__ void initcopy_kernel(const float* __restrict__ h0, float* __restrict__ H) {
    int i = blockIdx.x * blockDim.x + threadIdx.x;
    if (i < NN * DD / 4) {
        float4 v = reinterpret_cast<const float4*>(h0)[i];
        reinterpret_cast<float4*>(H)[i] = v;
        reinterpret_cast<float4*>(g_Y)[i] = v;
    }
}

// ---------------------------------------------------------------------------
// one-time partial U^T Y for the very first evaluation
// grid: NB blocks x 256 threads. thread owns (d = tx&127, k in [kb, kb+8))
// ---------------------------------------------------------------------------
__global__ void gpartial0_kernel(const float* __restrict__ U) {
    int tx = threadIdx.x, bid = blockIdx.x;
    int d = tx & 127, kb = (tx >> 7) * 8;
    float f[8];
#pragma unroll
    for (int k = 0; k < 8; k++) f[k] = 0.f;
    int row0 = bid * 128;
    int rmax = min(128, NN - row0);
    for (int r = 0; r < rmax; r++) {
        int n = row0 + r;
        float yv = g_Y[n * DD + d];
#pragma unroll
        for (int k = 0; k < 8; k++) f[k] = fmaf(__ldg(&U[n * KE + kb + k]), yv, f[k]);
    }
#pragma unroll
    for (int k = 0; k < 8; k++) g_part[bid * (KE * DD) + (kb + k) * DD + d] = f[k];
}

// ---------------------------------------------------------------------------
// reduce partials -> G  (deterministic, no atomics). grid: 8 x 256
// ---------------------------------------------------------------------------
__global__ void greduce_kernel() {
    int e = blockIdx.x * blockDim.x + threadIdx.x;  // 0..2047
    float s = 0.f;
#pragma unroll 4
    for (int b = 0; b < NB; b++) s += g_part[b * (KE * DD) + e];
    g_G[e] = s;
}

// ---------------------------------------------------------------------------
// helpers for the fused kernel
// ---------------------------------------------------------------------------
__device__ __forceinline__ void load_w(float* sW, const float* __restrict__ W, int tx) {
#pragma unroll
    for (int it = 0; it < 16; ++it) {
        int idx = tx + 256 * it;          // 4096 float4 slots
        int r = idx >> 5, q = idx & 31;
        float4 v = __ldg(&reinterpret_cast<const float4*>(W)[idx]);
        *reinterpret_cast<float4*>(&sW[r * SP + q * 4]) = v;
    }
}

// 128x128x128 tile GEMM: acc[i][j] = sum_k A[tr+16i][k] * B[tc+16j][k]
__device__ __forceinline__ void gemm_tile(const float* __restrict__ A, const float* __restrict__ B,
                                          int tr, int tc, float acc[8][8]) {
#pragma unroll
    for (int i = 0; i < 8; i++)
#pragma unroll
        for (int j = 0; j < 8; j++) acc[i][j] = 0.f;
#pragma unroll 2
    for (int k2 = 0; k2 < 64; k2++) {
        float2 a[8], b[8];
#pragma unroll
        for (int i = 0; i < 8; i++)
            a[i] = *reinterpret_cast<const float2*>(&A[(tr + 16 * i) * SP + 2 * k2]);
#pragma unroll
        for (int j = 0; j < 8; j++)
            b[j] = *reinterpret_cast<const float2*>(&B[(tc + 16 * j) * SP + 2 * k2]);
#pragma unroll
        for (int i = 0; i < 8; i++)
#pragma unroll
            for (int j = 0; j < 8; j++) {
                acc[i][j] = fmaf(a[i].x, b[j].x, acc[i][j]);
                acc[i][j] = fmaf(a[i].y, b[j].y, acc[i][j]);
            }
    }
}

// ---------------------------------------------------------------------------
// fused stage kernel: k = f(t, Y); RK4 update; partial U^T Y_next
// mode 0: acc = k;       Y = H + 0.5dt k
// mode 1: acc += 2k;     Y = H + 0.5dt k
// mode 2: acc += 2k;     Y = H + dt k
// mode 3: H += dt/6 (acc + k); Y = H (and write d_out)
// ---------------------------------------------------------------------------
__global__ __launch_bounds__(256, 1) void fused_kernel(
    const float* H, const float* __restrict__ U,
    const float* __restrict__ Wz, const float* __restrict__ bz,
    const float* __restrict__ Wr, const float* __restrict__ br,
    const float* __restrict__ Wc, const float* __restrict__ bc,
    const float* __restrict__ Wt, const float* __restrict__ bt,
    const float* __restrict__ mup,
    float* Hout, int mode, float t) {
    extern __shared__ float smem[];
    float* sW = smem;                 // 128*SP
    float* sY = sW + 128 * SP;        // 128*SP
    float* sRY = sY + 128 * SP;       // 128*SP
    float* sU = sRY + 128 * SP;       // 128*UP
    float* sG = sU + 128 * UP;        // 16*SP

    const int tx = threadIdx.x;
    const int bid = blockIdx.x;
    const int row0 = bid * 128;

    // ---- tile loads (Y, U, G), then Wr ----
#pragma unroll
    for (int it = 0; it < 16; ++it) {
        int idx = tx + 256 * it;
        int r = idx >> 5, q = idx & 31;
        int n = row0 + r;
        float4 v = make_float4(0.f, 0.f, 0.f, 0.f);
        if (n < NN) v = reinterpret_cast<const float4*>(g_Y)[n * 32 + q];
        *reinterpret_cast<float4*>(&sY[r * SP + q * 4]) = v;
    }
#pragma unroll
    for (int it = 0; it < 8; ++it) {
        int idx = tx + 256 * it;
        int r = idx >> 4, k = idx & 15;
        int n = row0 + r;
        sU[r * UP + k] = (n < NN) ? __ldg(&U[n * KE + k]) : 0.f;
    }
#pragma unroll
    for (int it = 0; it < 8; ++it) {
        int idx = tx + 256 * it;
        int k = idx >> 7, d = idx & 127;
        sG[k * SP + d] = g_G[idx];
    }
    load_w(sW, Wr, tx);
    __syncthreads();

    const int tr = tx & 15;
    const int tc = tx >> 4;

    float accA[8][8];   // r-acc, then reused as (1 - z)
    float cc[8][8];     // candidate

    // ---- R phase: r = sigmoid(Y Wr^T + br); sRY = r * y ----
    gemm_tile(sY, sW, tr, tc, accA);
#pragma unroll
    for (int j = 0; j < 8; j++) {
        int d = tc + 16 * j;
        float brv = __ldg(&br[d]);
#pragma unroll
        for (int i = 0; i < 8; i++) {
            int r = tr + 16 * i;
            float rv = sigm(accA[i][j] + brv);
            sRY[r * SP + d] = rv * sY[r * SP + d];
        }
    }
    __syncthreads();
    load_w(sW, Wz, tx);
    __syncthreads();

    // ---- Z phase: oz = 1 - sigmoid(Y Wz^T + bz) ----
    gemm_tile(sY, sW, tr, tc, accA);
#pragma unroll
    for (int j = 0; j < 8; j++) {
        int d = tc + 16 * j;
        float bzv = __ldg(&bz[d]);
#pragma unroll
        for (int i = 0; i < 8; i++) accA[i][j] = 1.0f - sigm(accA[i][j] + bzv);
    }
    __syncthreads();
    load_w(sW, Wc, tx);
    __syncthreads();

    // ---- C phase: c = tanh((r*y) Wc^T + bc) ----
    gemm_tile(sRY, sW, tr, tc, cc);

    float mu = __ldg(mup);
    float tm[8];
#pragma unroll
    for (int j = 0; j < 8; j++) {
        int d = tc + 16 * j;
        float bcv = __ldg(&bc[d]);
        tm[j] = tanhf(t * __ldg(&Wt[d]) + __ldg(&bt[d]));
#pragma unroll
        for (int i = 0; i < 8; i++) cc[i][j] = tanhf(cc[i][j] + bcv);
    }

    // ---- smooth + dh; write k into sY (exclusive per-element ownership) ----
#pragma unroll
    for (int i = 0; i < 8; i++) {
        int r = tr + 16 * i;
        float u[KE];
#pragma unroll
        for (int k = 0; k < KE; k++) u[k] = sU[r * UP + k];
#pragma unroll
        for (int j = 0; j < 8; j++) {
            int d = tc + 16 * j;
            float s = 0.f;
#pragma unroll
            for (int k = 0; k < KE; k++) s = fmaf(u[k], sG[k * SP + d], s);
            float y = sY[r * SP + d];
            float dh = accA[i][j] * (cc[i][j] + tm[j] - y) - mu * (y - s);
            sY[r * SP + d] = dh;
        }
    }
    __syncthreads();

    // ---- coalesced RK4 epilogue; write Y_next back into sY for partial-G ----
#pragma unroll
    for (int it = 0; it < 16; ++it) {
        int idx = tx + 256 * it;
        int r = idx >> 5, q = idx & 31;
        int n = row0 + r;
        float4 kv = *reinterpret_cast<float4*>(&sY[r * SP + q * 4]);
        float4 yn = make_float4(0.f, 0.f, 0.f, 0.f);
        if (n < NN) {
            int g = n * 32 + q;
            float4 h4 = reinterpret_cast<const float4*>(H)[g];
            if (mode == 0) {
                reinterpret_cast<float4*>(g_acc)[g] = kv;
                yn.x = fmaf(0.05f, kv.x, h4.x); yn.y = fmaf(0.05f, kv.y, h4.y);
                yn.z = fmaf(0.05f, kv.z, h4.z); yn.w = fmaf(0.05f, kv.w, h4.w);
            } else if (mode < 3) {
                float4 a4 = reinterpret_cast<float4*>(g_acc)[g];
                a4.x += 2.f * kv.x; a4.y += 2.f * kv.y;
                a4.z += 2.f * kv.z; a4.w += 2.f * kv.w;
                reinterpret_cast<float4*>(g_acc)[g] = a4;
                float cy = (mode == 1) ? 0.05f : 0.1f;
                yn.x = fmaf(cy, kv.x, h4.x); yn.y = fmaf(cy, kv.y, h4.y);
                yn.z = fmaf(cy, kv.z, h4.z); yn.w = fmaf(cy, kv.w, h4.w);
            } else {
                float4 a4 = reinterpret_cast<float4*>(g_acc)[g];
                const float c6 = DTS / 6.0f;
                yn.x = fmaf(c6, a4.x + kv.x, h4.x);
                yn.y = fmaf(c6, a4.y + kv.y, h4.y);
                yn.z = fmaf(c6, a4.z + kv.z, h4.z);
                yn.w = fmaf(c6, a4.w + kv.w, h4.w);
                reinterpret_cast<float4*>(Hout)[g] = yn;
            }
            reinterpret_cast<float4*>(g_Y)[g] = yn;
        }
        *reinterpret_cast<float4*>(&sY[r * SP + q * 4]) = yn;  // 0 for OOB rows
    }
    __syncthreads();

    // ---- fused partial G for the next stage: part = U_tile^T Y_next ----
    {
        int d = tx & 127, kb = (tx >> 7) * 8;
        float f[8];
#pragma unroll
        for (int k = 0; k < 8; k++) f[k] = 0.f;
        for (int r = 0; r < 128; r++) {
            float yv = sY[r * SP + d];
#pragma unroll
            for (int k = 0; k < 8; k++) f[k] = fmaf(sU[r * UP + kb + k], yv, f[k]);
        }
#pragma unroll
        for (int k = 0; k < 8; k++) g_part[bid * (KE * DD) + (kb + k) * DD + d] = f[k];
    }
}

// ---------------------------------------------------------------------------
extern "C" void kernel_launch(void* const* d_in, const int* in_sizes, int n_in,
                              void* d_out, int out_size) {
    const float* h0 = (const float*)d_in[0];
    const float* U  = (const float*)d_in[1];
    const float* Wz = (const float*)d_in[2];
    const float* bz = (const float*)d_in[3];
    const float* Wr = (const float*)d_in[4];
    const float* br = (const float*)d_in[5];
    const float* Wc = (const float*)d_in[6];
    const float* bc = (const float*)d_in[7];
    const float* Wt = (const float*)d_in[8];
    const float* bt = (const float*)d_in[9];
    const float* mu = (const float*)d_in[10];
    float* H = (float*)d_out;

    const size_t smembytes = (size_t)(3 * 128 * SP + 128 * UP + 16 * SP) * sizeof(float); // ~215 KB
    cudaError_t attr_rc = cudaFuncSetAttribute(
        fused_kernel, cudaFuncAttributeMaxDynamicSharedMemorySize, (int)smembytes);
    (void)attr_rc;  // idempotent, capture-legal non-stream API; consumed deliberately

    initcopy_kernel<<<(NN * DD / 4 + 255) / 256, 256>>>(h0, H);
    gpartial0_kernel<<<NB, 256>>>(U);

    for (int i = 0; i < 10; i++) {
        float tb = (float)i * DTS;
        float ts[4] = {tb, tb + 0.05f, tb + 0.05f, tb + 0.1f};
        for (int s = 0; s < 4; s++) {
            greduce_kernel<<<8, 256>>>();
            fused_kernel<<<NB, 256, smembytes>>>(H, U, Wz, bz, Wr, br, Wc, bc, Wt, bt,
                                                 mu, H, s, ts[s]);
        }
    }
}

// round 4
// speedup vs baseline: 1.0095x; 1.0095x over previous
#include <cuda_runtime.h>
#include <math.h>

#define NN 100000
#define DD 128
#define KE 16
#define NB 782            // ceil(NN/128)
#define DTS 0.1f
#define SP 132            // padded row stride (floats) for 128-wide tiles
#define UP 17             // padded row stride for U tile

// Scratch state (no allocations allowed) — ~109 MB total
__device__ float g_Y[NN * DD];        // current RK4 evaluation point
__device__ float g_acc[NN * DD];      // k1 + 2k2 + 2k3 accumulator
__device__ float g_part[NB * KE * DD];// per-block partial U^T Y
__device__ float g_G[KE * DD];        // reduced G = U^T Y

__device__ __forceinline__ float sigm(float x) { return 1.0f / (1.0f + __expf(-x)); }

// ---------------------------------------------------------------------------
// init: H (d_out) = Y = h0
// ---------------------------------------------------------------------------
__global__ void initcopy_kernel(const float* __restrict__ h0, float* __restrict__ H) {
    int i = blockIdx.x * blockDim.x + threadIdx.x;
    if (i < NN * DD / 4) {
        float4 v = reinterpret_cast<const float4*>(h0)[i];
        reinterpret_cast<float4*>(H)[i] = v;
        reinterpret_cast<float4*>(g_Y)[i] = v;
    }
}

// ---------------------------------------------------------------------------
// one-time partial U^T Y for the very first evaluation
// grid: NB blocks x 256 threads. thread owns (d = tx&127, k in [kb, kb+8))
// ---------------------------------------------------------------------------
__global__ void gpartial0_kernel(const float* __restrict__ U) {
    int tx = threadIdx.x, bid = blockIdx.x;
    int d = tx & 127, kb = (tx >> 7) * 8;
    float f[8];
#pragma unroll
    for (int k = 0; k < 8; k++) f[k] = 0.f;
    int row0 = bid * 128;
    int rmax = min(128, NN - row0);
    for (int r = 0; r < rmax; r++) {
        int n = row0 + r;
        float yv = g_Y[n * DD + d];
#pragma unroll
        for (int k = 0; k < 8; k++) f[k] = fmaf(__ldg(&U[n * KE + kb + k]), yv, f[k]);
    }
#pragma unroll
    for (int k = 0; k < 8; k++) g_part[bid * (KE * DD) + (kb + k) * DD + d] = f[k];
}

// ---------------------------------------------------------------------------
// reduce partials -> G  (deterministic, no atomics). grid: 8 x 256
// ---------------------------------------------------------------------------
__global__ void greduce_kernel() {
    int e = blockIdx.x * blockDim.x + threadIdx.x;  // 0..2047
    float s = 0.f;
#pragma unroll 4
    for (int b = 0; b < NB; b++) s += g_part[b * (KE * DD) + e];
    g_G[e] = s;
}

// ---------------------------------------------------------------------------
// helpers for the fused kernel
// ---------------------------------------------------------------------------
__device__ __forceinline__ void load_w(float* sW, const float* __restrict__ W, int tx) {
#pragma unroll
    for (int it = 0; it < 16; ++it) {
        int idx = tx + 256 * it;          // 4096 float4 slots
        int r = idx >> 5, q = idx & 31;
        float4 v = __ldg(&reinterpret_cast<const float4*>(W)[idx]);
        *reinterpret_cast<float4*>(&sW[r * SP + q * 4]) = v;
    }
}

// 128x128x128 tile GEMM: acc[i][j] = sum_k A[tr+16i][k] * B[tc+16j][k]
__device__ __forceinline__ void gemm_tile(const float* __restrict__ A, const float* __restrict__ B,
                                          int tr, int tc, float acc[8][8]) {
#pragma unroll
    for (int i = 0; i < 8; i++)
#pragma unroll
        for (int j = 0; j < 8; j++) acc[i][j] = 0.f;
#pragma unroll 2
    for (int k2 = 0; k2 < 64; k2++) {
        float2 a[8], b[8];
#pragma unroll
        for (int i = 0; i < 8; i++)
            a[i] = *reinterpret_cast<const float2*>(&A[(tr + 16 * i) * SP + 2 * k2]);
#pragma unroll
        for (int j = 0; j < 8; j++)
            b[j] = *reinterpret_cast<const float2*>(&B[(tc + 16 * j) * SP + 2 * k2]);
#pragma unroll
        for (int i = 0; i < 8; i++)
#pragma unroll
            for (int j = 0; j < 8; j++) {
                acc[i][j] = fmaf(a[i].x, b[j].x, acc[i][j]);
                acc[i][j] = fmaf(a[i].y, b[j].y, acc[i][j]);
            }
    }
}

// ---------------------------------------------------------------------------
// fused stage kernel: k = f(t, Y); RK4 update; partial U^T Y_next
// mode 0: acc = k;       Y = H + 0.5dt k
// mode 1: acc += 2k;     Y = H + 0.5dt k
// mode 2: acc += 2k;     Y = H + dt k
// mode 3: H += dt/6 (acc + k); Y = H (and write d_out)
// ---------------------------------------------------------------------------
__global__ __launch_bounds__(256, 1) void fused_kernel(
    const float* H, const float* __restrict__ U,
    const float* __restrict__ Wz, const float* __restrict__ bz,
    const float* __restrict__ Wr, const float* __restrict__ br,
    const float* __restrict__ Wc, const float* __restrict__ bc,
    const float* __restrict__ Wt, const float* __restrict__ bt,
    const float* __restrict__ mup,
    float* Hout, int mode, float t) {
    extern __shared__ float smem[];
    float* sW = smem;                 // 128*SP
    float* sY = sW + 128 * SP;        // 128*SP
    float* sRY = sY + 128 * SP;       // 128*SP
    float* sU = sRY + 128 * SP;       // 128*UP
    float* sG = sU + 128 * UP;        // 16*SP

    const int tx = threadIdx.x;
    const int bid = blockIdx.x;
    const int row0 = bid * 128;

    // ---- tile loads (Y, U, G), then Wr ----
#pragma unroll
    for (int it = 0; it < 16; ++it) {
        int idx = tx + 256 * it;
        int r = idx >> 5, q = idx & 31;
        int n = row0 + r;
        float4 v = make_float4(0.f, 0.f, 0.f, 0.f);
        if (n < NN) v = reinterpret_cast<const float4*>(g_Y)[n * 32 + q];
        *reinterpret_cast<float4*>(&sY[r * SP + q * 4]) = v;
    }
#pragma unroll
    for (int it = 0; it < 8; ++it) {
        int idx = tx + 256 * it;
        int r = idx >> 4, k = idx & 15;
        int n = row0 + r;
        sU[r * UP + k] = (n < NN) ? __ldg(&U[n * KE + k]) : 0.f;
    }
#pragma unroll
    for (int it = 0; it < 8; ++it) {
        int idx = tx + 256 * it;
        int k = idx >> 7, d = idx & 127;
        sG[k * SP + d] = g_G[idx];
    }
    load_w(sW, Wr, tx);
    __syncthreads();

    const int tr = tx & 15;
    const int tc = tx >> 4;

    float accA[8][8];   // r-acc, then reused as (1 - z)
    float cc[8][8];     // candidate

    // ---- R phase: r = sigmoid(Y Wr^T + br); sRY = r * y ----
    gemm_tile(sY, sW, tr, tc, accA);
#pragma unroll
    for (int j = 0; j < 8; j++) {
        int d = tc + 16 * j;
        float brv = __ldg(&br[d]);
#pragma unroll
        for (int i = 0; i < 8; i++) {
            int r = tr + 16 * i;
            float rv = sigm(accA[i][j] + brv);
            sRY[r * SP + d] = rv * sY[r * SP + d];
        }
    }
    __syncthreads();
    load_w(sW, Wz, tx);
    __syncthreads();

    // ---- Z phase: oz = 1 - sigmoid(Y Wz^T + bz) ----
    gemm_tile(sY, sW, tr, tc, accA);
#pragma unroll
    for (int j = 0; j < 8; j++) {
        int d = tc + 16 * j;
        float bzv = __ldg(&bz[d]);
#pragma unroll
        for (int i = 0; i < 8; i++) accA[i][j] = 1.0f - sigm(accA[i][j] + bzv);
    }
    __syncthreads();
    load_w(sW, Wc, tx);
    __syncthreads();

    // ---- C phase: c = tanh((r*y) Wc^T + bc) ----
    gemm_tile(sRY, sW, tr, tc, cc);

    float mu = __ldg(mup);
    float tm[8];
#pragma unroll
    for (int j = 0; j < 8; j++) {
        int d = tc + 16 * j;
        float bcv = __ldg(&bc[d]);
        tm[j] = tanhf(t * __ldg(&Wt[d]) + __ldg(&bt[d]));
#pragma unroll
        for (int i = 0; i < 8; i++) cc[i][j] = tanhf(cc[i][j] + bcv);
    }

    // ---- smooth + dh; write k into sY (exclusive per-element ownership) ----
#pragma unroll
    for (int i = 0; i < 8; i++) {
        int r = tr + 16 * i;
        float u[KE];
#pragma unroll
        for (int k = 0; k < KE; k++) u[k] = sU[r * UP + k];
#pragma unroll
        for (int j = 0; j < 8; j++) {
            int d = tc + 16 * j;
            float s = 0.f;
#pragma unroll
            for (int k = 0; k < KE; k++) s = fmaf(u[k], sG[k * SP + d], s);
            float y = sY[r * SP + d];
            float dh = accA[i][j] * (cc[i][j] + tm[j] - y) - mu * (y - s);
            sY[r * SP + d] = dh;
        }
    }
    __syncthreads();

    // ---- coalesced RK4 epilogue; write Y_next back into sY for partial-G ----
#pragma unroll
    for (int it = 0; it < 16; ++it) {
        int idx = tx + 256 * it;
        int r = idx >> 5, q = idx & 31;
        int n = row0 + r;
        float4 kv = *reinterpret_cast<float4*>(&sY[r * SP + q * 4]);
        float4 yn = make_float4(0.f, 0.f, 0.f, 0.f);
        if (n < NN) {
            int g = n * 32 + q;
            float4 h4 = reinterpret_cast<const float4*>(H)[g];
            if (mode == 0) {
                reinterpret_cast<float4*>(g_acc)[g] = kv;
                yn.x = fmaf(0.05f, kv.x, h4.x); yn.y = fmaf(0.05f, kv.y, h4.y);
                yn.z = fmaf(0.05f, kv.z, h4.z); yn.w = fmaf(0.05f, kv.w, h4.w);
            } else if (mode < 3) {
                float4 a4 = reinterpret_cast<float4*>(g_acc)[g];
                a4.x += 2.f * kv.x; a4.y += 2.f * kv.y;
                a4.z += 2.f * kv.z; a4.w += 2.f * kv.w;
                reinterpret_cast<float4*>(g_acc)[g] = a4;
                float cy = (mode == 1) ? 0.05f : 0.1f;
                yn.x = fmaf(cy, kv.x, h4.x); yn.y = fmaf(cy, kv.y, h4.y);
                yn.z = fmaf(cy, kv.z, h4.z); yn.w = fmaf(cy, kv.w, h4.w);
            } else {
                float4 a4 = reinterpret_cast<float4*>(g_acc)[g];
                const float c6 = DTS / 6.0f;
                yn.x = fmaf(c6, a4.x + kv.x, h4.x);
                yn.y = fmaf(c6, a4.y + kv.y, h4.y);
                yn.z = fmaf(c6, a4.z + kv.z, h4.z);
                yn.w = fmaf(c6, a4.w + kv.w, h4.w);
                reinterpret_cast<float4*>(Hout)[g] = yn;
            }
            reinterpret_cast<float4*>(g_Y)[g] = yn;
        }
        *reinterpret_cast<float4*>(&sY[r * SP + q * 4]) = yn;  // 0 for OOB rows
    }
    __syncthreads();

    // ---- fused partial G for the next stage: part = U_tile^T Y_next ----
    {
        int d = tx & 127, kb = (tx >> 7) * 8;
        float f[8];
#pragma unroll
        for (int k = 0; k < 8; k++) f[k] = 0.f;
        for (int r = 0; r < 128; r++) {
            float yv = sY[r * SP + d];
#pragma unroll
            for (int k = 0; k < 8; k++) f[k] = fmaf(sU[r * UP + kb + k], yv, f[k]);
        }
#pragma unroll
        for (int k = 0; k < 8; k++) g_part[bid * (KE * DD) + (kb + k) * DD + d] = f[k];
    }
}

// ---------------------------------------------------------------------------
extern "C" void kernel_launch(void* const* d_in, const int* in_sizes, int n_in,
                              void* d_out, int out_size) {
    const float* h0 = (const float*)d_in[0];
    const float* U  = (const float*)d_in[1];
    const float* Wz = (const float*)d_in[2];
    const float* bz = (const float*)d_in[3];
    const float* Wr = (const float*)d_in[4];
    const float* br = (const float*)d_in[5];
    const float* Wc = (const float*)d_in[6];
    const float* bc = (const float*)d_in[7];
    const float* Wt = (const float*)d_in[8];
    const float* bt = (const float*)d_in[9];
    const float* mu = (const float*)d_in[10];
    float* H = (float*)d_out;

    const size_t smembytes = (size_t)(3 * 128 * SP + 128 * UP + 16 * SP) * sizeof(float); // ~215 KB
    cudaError_t attr_rc = cudaFuncSetAttribute(
        fused_kernel, cudaFuncAttributeMaxDynamicSharedMemorySize, (int)smembytes);
    (void)attr_rc;  // idempotent, capture-legal non-stream API; consumed deliberately

    initcopy_kernel<<<(NN * DD / 4 + 255) / 256, 256>>>(h0, H);
    gpartial0_kernel<<<NB, 256>>>(U);

    for (int i = 0; i < 10; i++) {
        float tb = (float)i * DTS;
        float ts[4] = {tb, tb + 0.05f, tb + 0.05f, tb + 0.1f};
        for (int s = 0; s < 4; s++) {
            greduce_kernel<<<8, 256>>>();
            fused_kernel<<<NB, 256, smembytes>>>(H, U, Wz, bz, Wr, br, Wc, bc, Wt, bt,
                                                 mu, H, s, ts[s]);
        }
    }
}

// round 5
// speedup vs baseline: 1.1036x; 1.0932x over previous
#include <cuda_runtime.h>
#include <math.h>

#define NN 100000
#define DD 128
#define KE 16
#define NB 782            // ceil(NN/128)
#define DTS 0.1f
#define SP 132            // padded row stride (floats); 528B rows, 16B-aligned
#define UP 17             // padded row stride for U tile

// Scratch state (no allocations allowed) — ~109 MB total
__device__ float g_Y[NN * DD];        // current RK4 evaluation point
__device__ float g_acc[NN * DD];      // k1 + 2k2 + 2k3 accumulator
__device__ float g_part[NB * KE * DD];// per-block partial U^T Y
__device__ float g_G[KE * DD];        // reduced G = U^T Y

__device__ __forceinline__ float sigm(float x) { return 1.0f / (1.0f + __expf(-x)); }

// ---------------------------------------------------------------------------
// init: H (d_out) = Y = h0
// ---------------------------------------------------------------------------
__global__ void initcopy_kernel(const float* __restrict__ h0, float* __restrict__ H) {
    int i = blockIdx.x * blockDim.x + threadIdx.x;
    if (i < NN * DD / 4) {
        float4 v = reinterpret_cast<const float4*>(h0)[i];
        reinterpret_cast<float4*>(H)[i] = v;
        reinterpret_cast<float4*>(g_Y)[i] = v;
    }
}

// ---------------------------------------------------------------------------
// one-time partial U^T Y for the very first evaluation
// ---------------------------------------------------------------------------
__global__ void gpartial0_kernel(const float* __restrict__ U) {
    int tx = threadIdx.x, bid = blockIdx.x;
    int d = tx & 127, kb = (tx >> 7) * 8;
    float f[8];
#pragma unroll
    for (int k = 0; k < 8; k++) f[k] = 0.f;
    int row0 = bid * 128;
    int rmax = min(128, NN - row0);
    for (int r = 0; r < rmax; r++) {
        int n = row0 + r;
        float yv = g_Y[n * DD + d];
#pragma unroll
        for (int k = 0; k < 8; k++) f[k] = fmaf(__ldg(&U[n * KE + kb + k]), yv, f[k]);
    }
#pragma unroll
    for (int k = 0; k < 8; k++) g_part[bid * (KE * DD) + (kb + k) * DD + d] = f[k];
}

// ---------------------------------------------------------------------------
// reduce partials -> G. 4 independent chains for MLP; fixed order => deterministic
// grid: 8 x 256 (one thread per element e)
// ---------------------------------------------------------------------------
__global__ void greduce_kernel() {
    int e = blockIdx.x * blockDim.x + threadIdx.x;  // 0..2047
    float s0 = 0.f, s1 = 0.f, s2 = 0.f, s3 = 0.f;
    int b = 0;
#pragma unroll 4
    for (; b + 4 <= NB; b += 4) {
        s0 += g_part[(b + 0) * (KE * DD) + e];
        s1 += g_part[(b + 1) * (KE * DD) + e];
        s2 += g_part[(b + 2) * (KE * DD) + e];
        s3 += g_part[(b + 3) * (KE * DD) + e];
    }
    for (; b < NB; ++b) s0 += g_part[b * (KE * DD) + e];
    g_G[e] = (s0 + s1) + (s2 + s3);
}

// ---------------------------------------------------------------------------
// helpers for the fused kernel
// ---------------------------------------------------------------------------
__device__ __forceinline__ void load_w(float* sW, const float* __restrict__ W, int tx) {
#pragma unroll
    for (int it = 0; it < 16; ++it) {
        int idx = tx + 256 * it;          // 4096 float4 slots
        int r = idx >> 5, q = idx & 31;
        float4 v = __ldg(&reinterpret_cast<const float4*>(W)[idx]);
        *reinterpret_cast<float4*>(&sW[r * SP + q * 4]) = v;
    }
}

// 128x128x128 tile GEMM, float4 fragments (LDS.128), k-step 4.
// acc[i][j] = sum_k A[tr+16i][k] * B[tc+16j][k]
__device__ __forceinline__ void gemm_tile(const float* __restrict__ A, const float* __restrict__ B,
                                          int tr, int tc, float acc[8][8]) {
#pragma unroll
    for (int i = 0; i < 8; i++)
#pragma unroll
        for (int j = 0; j < 8; j++) acc[i][j] = 0.f;
#pragma unroll 1
    for (int k4 = 0; k4 < 32; k4++) {
        float4 a[8], b[8];
#pragma unroll
        for (int i = 0; i < 8; i++)
            a[i] = *reinterpret_cast<const float4*>(&A[(tr + 16 * i) * SP + 4 * k4]);
#pragma unroll
        for (int j = 0; j < 8; j++)
            b[j] = *reinterpret_cast<const float4*>(&B[(tc + 16 * j) * SP + 4 * k4]);
#pragma unroll
        for (int i = 0; i < 8; i++)
#pragma unroll
            for (int j = 0; j < 8; j++) {
                acc[i][j] = fmaf(a[i].x, b[j].x, acc[i][j]);
                acc[i][j] = fmaf(a[i].y, b[j].y, acc[i][j]);
                acc[i][j] = fmaf(a[i].z, b[j].z, acc[i][j]);
                acc[i][j] = fmaf(a[i].w, b[j].w, acc[i][j]);
            }
    }
}

// ---------------------------------------------------------------------------
// fused stage kernel: k = f(t, Y); RK4 update; partial U^T Y_next
// Phase order R -> C -> Z keeps exactly ONE 8x8 accumulator live (no spills).
// mode 0: acc = k;       Y = H + 0.5dt k
// mode 1: acc += 2k;     Y = H + 0.5dt k
// mode 2: acc += 2k;     Y = H + dt k
// mode 3: H += dt/6 (acc + k); Y = H (and write d_out)
// ---------------------------------------------------------------------------
__global__ __launch_bounds__(256, 1) void fused_kernel(
    const float* H, const float* __restrict__ U,
    const float* __restrict__ Wz, const float* __restrict__ bz,
    const float* __restrict__ Wr, const float* __restrict__ br,
    const float* __restrict__ Wc, const float* __restrict__ bc,
    const float* __restrict__ Wt, const float* __restrict__ bt,
    const float* __restrict__ mup,
    float* Hout, int mode, float t) {
    extern __shared__ float smem[];
    float* sW = smem;                 // 128*SP
    float* sY = sW + 128 * SP;        // 128*SP
    float* sRY = sY + 128 * SP;       // 128*SP (r*y, later c+t_mod)
    float* sU = sRY + 128 * SP;       // 128*UP
    float* sG = sU + 128 * UP;        // 16*SP

    const int tx = threadIdx.x;
    const int bid = blockIdx.x;
    const int row0 = bid * 128;

    // ---- tile loads (Y, U, G), then Wr ----
#pragma unroll
    for (int it = 0; it < 16; ++it) {
        int idx = tx + 256 * it;
        int r = idx >> 5, q = idx & 31;
        int n = row0 + r;
        float4 v = make_float4(0.f, 0.f, 0.f, 0.f);
        if (n < NN) v = reinterpret_cast<const float4*>(g_Y)[n * 32 + q];
        *reinterpret_cast<float4*>(&sY[r * SP + q * 4]) = v;
    }
#pragma unroll
    for (int it = 0; it < 8; ++it) {
        int idx = tx + 256 * it;
        int r = idx >> 4, k = idx & 15;
        int n = row0 + r;
        sU[r * UP + k] = (n < NN) ? __ldg(&U[n * KE + k]) : 0.f;
    }
#pragma unroll
    for (int it = 0; it < 8; ++it) {
        int idx = tx + 256 * it;
        int k = idx >> 7, d = idx & 127;
        sG[k * SP + d] = g_G[idx];
    }
    load_w(sW, Wr, tx);
    __syncthreads();

    const int tr = tx & 15;
    const int tc = tx >> 4;

    float acc[8][8];    // the single live accumulator

    // ---- R phase: r = sigmoid(Y Wr^T + br); sRY = r * y ----
    gemm_tile(sY, sW, tr, tc, acc);
#pragma unroll
    for (int j = 0; j < 8; j++) {
        int d = tc + 16 * j;
        float brv = __ldg(&br[d]);
#pragma unroll
        for (int i = 0; i < 8; i++) {
            int r = tr + 16 * i;
            float rv = sigm(acc[i][j] + brv);
            sRY[r * SP + d] = rv * sY[r * SP + d];
        }
    }
    __syncthreads();
    load_w(sW, Wc, tx);
    __syncthreads();

    // ---- C phase: c = tanh((r*y) Wc^T + bc); park c + t_mod into sRY ----
    gemm_tile(sRY, sW, tr, tc, acc);
    __syncthreads();   // all threads done reading sRY before overwrite
#pragma unroll
    for (int j = 0; j < 8; j++) {
        int d = tc + 16 * j;
        float bcv = __ldg(&bc[d]);
        float tmv = tanhf(t * __ldg(&Wt[d]) + __ldg(&bt[d]));
#pragma unroll
        for (int i = 0; i < 8; i++) {
            int r = tr + 16 * i;
            sRY[r * SP + d] = tanhf(acc[i][j] + bcv) + tmv;  // exclusive slot
        }
    }
    __syncthreads();
    load_w(sW, Wz, tx);
    __syncthreads();

    // ---- Z phase: oz = 1 - sigmoid(Y Wz^T + bz) ----
    gemm_tile(sY, sW, tr, tc, acc);
    float mu = __ldg(mup);
#pragma unroll
    for (int j = 0; j < 8; j++) {
        int d = tc + 16 * j;
        float bzv = __ldg(&bz[d]);
#pragma unroll
        for (int i = 0; i < 8; i++) acc[i][j] = 1.0f - sigm(acc[i][j] + bzv);
    }
    __syncthreads();   // all threads done reading sY before overwrite

    // ---- smooth + dh; write k into sY (exclusive per-element ownership) ----
#pragma unroll
    for (int i = 0; i < 8; i++) {
        int r = tr + 16 * i;
        float u[KE];
#pragma unroll
        for (int k = 0; k < KE; k++) u[k] = sU[r * UP + k];
#pragma unroll
        for (int j = 0; j < 8; j++) {
            int d = tc + 16 * j;
            float s = 0.f;
#pragma unroll
            for (int k = 0; k < KE; k++) s = fmaf(u[k], sG[k * SP + d], s);
            float y = sY[r * SP + d];
            float dh = acc[i][j] * (sRY[r * SP + d] - y) - mu * (y - s);
            sY[r * SP + d] = dh;
        }
    }
    __syncthreads();

    // ---- coalesced RK4 epilogue; write Y_next back into sY for partial-G ----
#pragma unroll
    for (int it = 0; it < 16; ++it) {
        int idx = tx + 256 * it;
        int r = idx >> 5, q = idx & 31;
        int n = row0 + r;
        float4 kv = *reinterpret_cast<float4*>(&sY[r * SP + q * 4]);
        float4 yn = make_float4(0.f, 0.f, 0.f, 0.f);
        if (n < NN) {
            int g = n * 32 + q;
            float4 h4 = reinterpret_cast<const float4*>(H)[g];
            if (mode == 0) {
                reinterpret_cast<float4*>(g_acc)[g] = kv;
                yn.x = fmaf(0.05f, kv.x, h4.x); yn.y = fmaf(0.05f, kv.y, h4.y);
                yn.z = fmaf(0.05f, kv.z, h4.z); yn.w = fmaf(0.05f, kv.w, h4.w);
            } else if (mode < 3) {
                float4 a4 = reinterpret_cast<float4*>(g_acc)[g];
                a4.x += 2.f * kv.x; a4.y += 2.f * kv.y;
                a4.z += 2.f * kv.z; a4.w += 2.f * kv.w;
                reinterpret_cast<float4*>(g_acc)[g] = a4;
                float cy = (mode == 1) ? 0.05f : 0.1f;
                yn.x = fmaf(cy, kv.x, h4.x); yn.y = fmaf(cy, kv.y, h4.y);
                yn.z = fmaf(cy, kv.z, h4.z); yn.w = fmaf(cy, kv.w, h4.w);
            } else {
                float4 a4 = reinterpret_cast<float4*>(g_acc)[g];
                const float c6 = DTS / 6.0f;
                yn.x = fmaf(c6, a4.x + kv.x, h4.x);
                yn.y = fmaf(c6, a4.y + kv.y, h4.y);
                yn.z = fmaf(c6, a4.z + kv.z, h4.z);
                yn.w = fmaf(c6, a4.w + kv.w, h4.w);
                reinterpret_cast<float4*>(Hout)[g] = yn;
            }
            reinterpret_cast<float4*>(g_Y)[g] = yn;
        }
        *reinterpret_cast<float4*>(&sY[r * SP + q * 4]) = yn;  // 0 for OOB rows
    }
    __syncthreads();

    // ---- fused partial G for the next stage: part = U_tile^T Y_next ----
    {
        int d = tx & 127, kb = (tx >> 7) * 8;
        float f[8];
#pragma unroll
        for (int k = 0; k < 8; k++) f[k] = 0.f;
        for (int r = 0; r < 128; r++) {
            float yv = sY[r * SP + d];
#pragma unroll
            for (int k = 0; k < 8; k++) f[k] = fmaf(sU[r * UP + kb + k], yv, f[k]);
        }
#pragma unroll
        for (int k = 0; k < 8; k++) g_part[bid * (KE * DD) + (kb + k) * DD + d] = f[k];
    }
}

// ---------------------------------------------------------------------------
extern "C" void kernel_launch(void* const* d_in, const int* in_sizes, int n_in,
                              void* d_out, int out_size) {
    const float* h0 = (const float*)d_in[0];
    const float* U  = (const float*)d_in[1];
    const float* Wz = (const float*)d_in[2];
    const float* bz = (const float*)d_in[3];
    const float* Wr = (const float*)d_in[4];
    const float* br = (const float*)d_in[5];
    const float* Wc = (const float*)d_in[6];
    const float* bc = (const float*)d_in[7];
    const float* Wt = (const float*)d_in[8];
    const float* bt = (const float*)d_in[9];
    const float* mu = (const float*)d_in[10];
    float* H = (float*)d_out;

    const size_t smembytes = (size_t)(3 * 128 * SP + 128 * UP + 16 * SP) * sizeof(float); // ~215 KB
    cudaError_t attr_rc = cudaFuncSetAttribute(
        fused_kernel, cudaFuncAttributeMaxDynamicSharedMemorySize, (int)smembytes);
    (void)attr_rc;

    initcopy_kernel<<<(NN * DD / 4 + 255) / 256, 256>>>(h0, H);
    gpartial0_kernel<<<NB, 256>>>(U);

    for (int i = 0; i < 10; i++) {
        float tb = (float)i * DTS;
        float ts[4] = {tb, tb + 0.05f, tb + 0.05f, tb + 0.1f};
        for (int s = 0; s < 4; s++) {
            greduce_kernel<<<8, 256>>>();
            fused_kernel<<<NB, 256, smembytes>>>(H, U, Wz, bz, Wr, br, Wc, bc, Wt, bt,
                                                 mu, H, s, ts[s]);
        }
    }
}

// round 6
// speedup vs baseline: 1.1039x; 1.0003x over previous
#include <cuda_runtime.h>
#include <math.h>

#define NN 100000
#define DD 128
#define KE 16
#define NB 782            // ceil(NN/128)
#define DTS 0.1f
#define SP 132            // padded row stride (floats); 528B rows, 16B-aligned
#define UP 17             // padded row stride for U tile

// Scratch state (no allocations allowed) — ~109 MB total
__device__ float g_Y[NN * DD];        // current RK4 evaluation point
__device__ float g_acc[NN * DD];      // k1 + 2k2 + 2k3 accumulator
__device__ float g_part[NB * KE * DD];// per-block partial U^T Y
__device__ float g_G[KE * DD];        // reduced G = U^T Y

__device__ __forceinline__ float sigm(float x) { return 1.0f / (1.0f + __expf(-x)); }

// ---------------------------------------------------------------------------
// init: H (d_out) = Y = h0
// ---------------------------------------------------------------------------
__global__ void initcopy_kernel(const float* __restrict__ h0, float* __restrict__ H) {
    int i = blockIdx.x * blockDim.x + threadIdx.x;
    if (i < NN * DD / 4) {
        float4 v = reinterpret_cast<const float4*>(h0)[i];
        reinterpret_cast<float4*>(H)[i] = v;
        reinterpret_cast<float4*>(g_Y)[i] = v;
    }
}

// ---------------------------------------------------------------------------
// one-time partial U^T Y for the very first evaluation
// ---------------------------------------------------------------------------
__global__ void gpartial0_kernel(const float* __restrict__ U) {
    int tx = threadIdx.x, bid = blockIdx.x;
    int d = tx & 127, kb = (tx >> 7) * 8;
    float f[8];
#pragma unroll
    for (int k = 0; k < 8; k++) f[k] = 0.f;
    int row0 = bid * 128;
    int rmax = min(128, NN - row0);
    for (int r = 0; r < rmax; r++) {
        int n = row0 + r;
        float yv = g_Y[n * DD + d];
#pragma unroll
        for (int k = 0; k < 8; k++) f[k] = fmaf(__ldg(&U[n * KE + kb + k]), yv, f[k]);
    }
#pragma unroll
    for (int k = 0; k < 8; k++) g_part[bid * (KE * DD) + (kb + k) * DD + d] = f[k];
}

// ---------------------------------------------------------------------------
// reduce partials -> G. 4 independent chains for MLP; fixed order => deterministic
// grid: 8 x 256 (one thread per element e)
// ---------------------------------------------------------------------------
__global__ void greduce_kernel() {
    int e = blockIdx.x * blockDim.x + threadIdx.x;  // 0..2047
    float s0 = 0.f, s1 = 0.f, s2 = 0.f, s3 = 0.f;
    int b = 0;
#pragma unroll 4
    for (; b + 4 <= NB; b += 4) {
        s0 += g_part[(b + 0) * (KE * DD) + e];
        s1 += g_part[(b + 1) * (KE * DD) + e];
        s2 += g_part[(b + 2) * (KE * DD) + e];
        s3 += g_part[(b + 3) * (KE * DD) + e];
    }
    for (; b < NB; ++b) s0 += g_part[b * (KE * DD) + e];
    g_G[e] = (s0 + s1) + (s2 + s3);
}

// ---------------------------------------------------------------------------
// helpers for the fused kernel
// ---------------------------------------------------------------------------
__device__ __forceinline__ void load_w(float* sW, const float* __restrict__ W, int tx) {
#pragma unroll
    for (int it = 0; it < 16; ++it) {
        int idx = tx + 256 * it;          // 4096 float4 slots
        int r = idx >> 5, q = idx & 31;
        float4 v = __ldg(&reinterpret_cast<const float4*>(W)[idx]);
        *reinterpret_cast<float4*>(&sW[r * SP + q * 4]) = v;
    }
}

// 128x128x128 tile GEMM, float4 fragments (LDS.128), k-step 4.
// acc[i][j] = sum_k A[tr+16i][k] * B[tc+16j][k]
__device__ __forceinline__ void gemm_tile(const float* __restrict__ A, const float* __restrict__ B,
                                          int tr, int tc, float acc[8][8]) {
#pragma unroll
    for (int i = 0; i < 8; i++)
#pragma unroll
        for (int j = 0; j < 8; j++) acc[i][j] = 0.f;
#pragma unroll 1
    for (int k4 = 0; k4 < 32; k4++) {
        float4 a[8], b[8];
#pragma unroll
        for (int i = 0; i < 8; i++)
            a[i] = *reinterpret_cast<const float4*>(&A[(tr + 16 * i) * SP + 4 * k4]);
#pragma unroll
        for (int j = 0; j < 8; j++)
            b[j] = *reinterpret_cast<const float4*>(&B[(tc + 16 * j) * SP + 4 * k4]);
#pragma unroll
        for (int i = 0; i < 8; i++)
#pragma unroll
            for (int j = 0; j < 8; j++) {
                acc[i][j] = fmaf(a[i].x, b[j].x, acc[i][j]);
                acc[i][j] = fmaf(a[i].y, b[j].y, acc[i][j]);
                acc[i][j] = fmaf(a[i].z, b[j].z, acc[i][j]);
                acc[i][j] = fmaf(a[i].w, b[j].w, acc[i][j]);
            }
    }
}

// ---------------------------------------------------------------------------
// fused stage kernel: k = f(t, Y); RK4 update; partial U^T Y_next
// Phase order R -> C -> Z keeps exactly ONE 8x8 accumulator live (no spills).
// mode 0: acc = k;       Y = H + 0.5dt k
// mode 1: acc += 2k;     Y = H + 0.5dt k
// mode 2: acc += 2k;     Y = H + dt k
// mode 3: H += dt/6 (acc + k); Y = H (and write d_out)
// ---------------------------------------------------------------------------
__global__ __launch_bounds__(256, 1) void fused_kernel(
    const float* H, const float* __restrict__ U,
    const float* __restrict__ Wz, const float* __restrict__ bz,
    const float* __restrict__ Wr, const float* __restrict__ br,
    const float* __restrict__ Wc, const float* __restrict__ bc,
    const float* __restrict__ Wt, const float* __restrict__ bt,
    const float* __restrict__ mup,
    float* Hout, int mode, float t) {
    extern __shared__ float smem[];
    float* sW = smem;                 // 128*SP
    float* sY = sW + 128 * SP;        // 128*SP
    float* sRY = sY + 128 * SP;       // 128*SP (r*y, later c+t_mod)
    float* sU = sRY + 128 * SP;       // 128*UP
    float* sG = sU + 128 * UP;        // 16*SP

    const int tx = threadIdx.x;
    const int bid = blockIdx.x;
    const int row0 = bid * 128;

    // ---- tile loads (Y, U, G), then Wr ----
#pragma unroll
    for (int it = 0; it < 16; ++it) {
        int idx = tx + 256 * it;
        int r = idx >> 5, q = idx & 31;
        int n = row0 + r;
        float4 v = make_float4(0.f, 0.f, 0.f, 0.f);
        if (n < NN) v = reinterpret_cast<const float4*>(g_Y)[n * 32 + q];
        *reinterpret_cast<float4*>(&sY[r * SP + q * 4]) = v;
    }
#pragma unroll
    for (int it = 0; it < 8; ++it) {
        int idx = tx + 256 * it;
        int r = idx >> 4, k = idx & 15;
        int n = row0 + r;
        sU[r * UP + k] = (n < NN) ? __ldg(&U[n * KE + k]) : 0.f;
    }
#pragma unroll
    for (int it = 0; it < 8; ++it) {
        int idx = tx + 256 * it;
        int k = idx >> 7, d = idx & 127;
        sG[k * SP + d] = g_G[idx];
    }
    load_w(sW, Wr, tx);
    __syncthreads();

    const int tr = tx & 15;
    const int tc = tx >> 4;

    float acc[8][8];    // the single live accumulator

    // ---- R phase: r = sigmoid(Y Wr^T + br); sRY = r * y ----
    gemm_tile(sY, sW, tr, tc, acc);
#pragma unroll
    for (int j = 0; j < 8; j++) {
        int d = tc + 16 * j;
        float brv = __ldg(&br[d]);
#pragma unroll
        for (int i = 0; i < 8; i++) {
            int r = tr + 16 * i;
            float rv = sigm(acc[i][j] + brv);
            sRY[r * SP + d] = rv * sY[r * SP + d];
        }
    }
    __syncthreads();
    load_w(sW, Wc, tx);
    __syncthreads();

    // ---- C phase: c = tanh((r*y) Wc^T + bc); park c + t_mod into sRY ----
    gemm_tile(sRY, sW, tr, tc, acc);
    __syncthreads();   // all threads done reading sRY before overwrite
#pragma unroll
    for (int j = 0; j < 8; j++) {
        int d = tc + 16 * j;
        float bcv = __ldg(&bc[d]);
        float tmv = tanhf(t * __ldg(&Wt[d]) + __ldg(&bt[d]));
#pragma unroll
        for (int i = 0; i < 8; i++) {
            int r = tr + 16 * i;
            sRY[r * SP + d] = tanhf(acc[i][j] + bcv) + tmv;  // exclusive slot
        }
    }
    __syncthreads();
    load_w(sW, Wz, tx);
    __syncthreads();

    // ---- Z phase: oz = 1 - sigmoid(Y Wz^T + bz) ----
    gemm_tile(sY, sW, tr, tc, acc);
    float mu = __ldg(mup);
#pragma unroll
    for (int j = 0; j < 8; j++) {
        int d = tc + 16 * j;
        float bzv = __ldg(&bz[d]);
#pragma unroll
        for (int i = 0; i < 8; i++) acc[i][j] = 1.0f - sigm(acc[i][j] + bzv);
    }
    __syncthreads();   // all threads done reading sY before overwrite

    // ---- smooth + dh; write k into sY (exclusive per-element ownership) ----
#pragma unroll
    for (int i = 0; i < 8; i++) {
        int r = tr + 16 * i;
        float u[KE];
#pragma unroll
        for (int k = 0; k < KE; k++) u[k] = sU[r * UP + k];
#pragma unroll
        for (int j = 0; j < 8; j++) {
            int d = tc + 16 * j;
            float s = 0.f;
#pragma unroll
            for (int k = 0; k < KE; k++) s = fmaf(u[k], sG[k * SP + d], s);
            float y = sY[r * SP + d];
            float dh = acc[i][j] * (sRY[r * SP + d] - y) - mu * (y - s);
            sY[r * SP + d] = dh;
        }
    }
    __syncthreads();

    // ---- coalesced RK4 epilogue; write Y_next back into sY for partial-G ----
#pragma unroll
    for (int it = 0; it < 16; ++it) {
        int idx = tx + 256 * it;
        int r = idx >> 5, q = idx & 31;
        int n = row0 + r;
        float4 kv = *reinterpret_cast<float4*>(&sY[r * SP + q * 4]);
        float4 yn = make_float4(0.f, 0.f, 0.f, 0.f);
        if (n < NN) {
            int g = n * 32 + q;
            float4 h4 = reinterpret_cast<const float4*>(H)[g];
            if (mode == 0) {
                reinterpret_cast<float4*>(g_acc)[g] = kv;
                yn.x = fmaf(0.05f, kv.x, h4.x); yn.y = fmaf(0.05f, kv.y, h4.y);
                yn.z = fmaf(0.05f, kv.z, h4.z); yn.w = fmaf(0.05f, kv.w, h4.w);
            } else if (mode < 3) {
                float4 a4 = reinterpret_cast<float4*>(g_acc)[g];
                a4.x += 2.f * kv.x; a4.y += 2.f * kv.y;
                a4.z += 2.f * kv.z; a4.w += 2.f * kv.w;
                reinterpret_cast<float4*>(g_acc)[g] = a4;
                float cy = (mode == 1) ? 0.05f : 0.1f;
                yn.x = fmaf(cy, kv.x, h4.x); yn.y = fmaf(cy, kv.y, h4.y);
                yn.z = fmaf(cy, kv.z, h4.z); yn.w = fmaf(cy, kv.w, h4.w);
            } else {
                float4 a4 = reinterpret_cast<float4*>(g_acc)[g];
                const float c6 = DTS / 6.0f;
                yn.x = fmaf(c6, a4.x + kv.x, h4.x);
                yn.y = fmaf(c6, a4.y + kv.y, h4.y);
                yn.z = fmaf(c6, a4.z + kv.z, h4.z);
                yn.w = fmaf(c6, a4.w + kv.w, h4.w);
                reinterpret_cast<float4*>(Hout)[g] = yn;
            }
            reinterpret_cast<float4*>(g_Y)[g] = yn;
        }
        *reinterpret_cast<float4*>(&sY[r * SP + q * 4]) = yn;  // 0 for OOB rows
    }
    __syncthreads();

    // ---- fused partial G for the next stage: part = U_tile^T Y_next ----
    {
        int d = tx & 127, kb = (tx >> 7) * 8;
        float f[8];
#pragma unroll
        for (int k = 0; k < 8; k++) f[k] = 0.f;
        for (int r = 0; r < 128; r++) {
            float yv = sY[r * SP + d];
#pragma unroll
            for (int k = 0; k < 8; k++) f[k] = fmaf(sU[r * UP + kb + k], yv, f[k]);
        }
#pragma unroll
        for (int k = 0; k < 8; k++) g_part[bid * (KE * DD) + (kb + k) * DD + d] = f[k];
    }
}

// ---------------------------------------------------------------------------
extern "C" void kernel_launch(void* const* d_in, const int* in_sizes, int n_in,
                              void* d_out, int out_size) {
    const float* h0 = (const float*)d_in[0];
    const float* U  = (const float*)d_in[1];
    const float* Wz = (const float*)d_in[2];
    const float* bz = (const float*)d_in[3];
    const float* Wr = (const float*)d_in[4];
    const float* br = (const float*)d_in[5];
    const float* Wc = (const float*)d_in[6];
    const float* bc = (const float*)d_in[7];
    const float* Wt = (const float*)d_in[8];
    const float* bt = (const float*)d_in[9];
    const float* mu = (const float*)d_in[10];
    float* H = (float*)d_out;

    const size_t smembytes = (size_t)(3 * 128 * SP + 128 * UP + 16 * SP) * sizeof(float); // ~215 KB
    cudaError_t attr_rc = cudaFuncSetAttribute(
        fused_kernel, cudaFuncAttributeMaxDynamicSharedMemorySize, (int)smembytes);
    (void)attr_rc;

    initcopy_kernel<<<(NN * DD / 4 + 255) / 256, 256>>>(h0, H);
    gpartial0_kernel<<<NB, 256>>>(U);

    for (int i = 0; i < 10; i++) {
        float tb = (float)i * DTS;
        float ts[4] = {tb, tb + 0.05f, tb + 0.05f, tb + 0.1f};
        for (int s = 0; s < 4; s++) {
            greduce_kernel<<<8, 256>>>();
            fused_kernel<<<NB, 256, smembytes>>>(H, U, Wz, bz, Wr, br, Wc, bc, Wt, bt,
                                                 mu, H, s, ts[s]);
        }
    }
}

// round 7
// speedup vs baseline: 1.1085x; 1.0042x over previous
#include <cuda_runtime.h>
#include <math.h>

#define NN 100000
#define DD 128
#define KE 16
#define NB 782            // ceil(NN/128)
#define DTS 0.1f
#define SP 132            // padded row stride (floats); 528B rows, 16B-aligned
#define UP 17             // padded row stride for U tile

// Scratch state (no allocations allowed) — ~109 MB total
__device__ float g_Y[NN * DD];        // current RK4 evaluation point
__device__ float g_acc[NN * DD];      // k1 + 2k2 + 2k3 accumulator
__device__ float g_part[NB * KE * DD];// per-block partial U^T Y
__device__ float g_G[KE * DD];        // reduced G = U^T Y

__device__ __forceinline__ float sigm(float x) { return 1.0f / (1.0f + __expf(-x)); }

// ---------------------------------------------------------------------------
// init: H (d_out) = Y = h0
// ---------------------------------------------------------------------------
__global__ void initcopy_kernel(const float* __restrict__ h0, float* __restrict__ H) {
    int i = blockIdx.x * blockDim.x + threadIdx.x;
    if (i < NN * DD / 4) {
        float4 v = reinterpret_cast<const float4*>(h0)[i];
        reinterpret_cast<float4*>(H)[i] = v;
        reinterpret_cast<float4*>(g_Y)[i] = v;
    }
}

// ---------------------------------------------------------------------------
// one-time partial U^T Y for the very first evaluation
// ---------------------------------------------------------------------------
__global__ void gpartial0_kernel(const float* __restrict__ U) {
    int tx = threadIdx.x, bid = blockIdx.x;
    int d = tx & 127, kb = (tx >> 7) * 8;
    float f[8];
#pragma unroll
    for (int k = 0; k < 8; k++) f[k] = 0.f;
    int row0 = bid * 128;
    int rmax = min(128, NN - row0);
    for (int r = 0; r < rmax; r++) {
        int n = row0 + r;
        float yv = g_Y[n * DD + d];
#pragma unroll
        for (int k = 0; k < 8; k++) f[k] = fmaf(__ldg(&U[n * KE + kb + k]), yv, f[k]);
    }
#pragma unroll
    for (int k = 0; k < 8; k++) g_part[bid * (KE * DD) + (kb + k) * DD + d] = f[k];
}

// ---------------------------------------------------------------------------
// reduce partials -> G. 4 independent chains for MLP; fixed order => deterministic
// grid: 8 x 256 (one thread per element e)
// ---------------------------------------------------------------------------
__global__ void greduce_kernel() {
    int e = blockIdx.x * blockDim.x + threadIdx.x;  // 0..2047
    float s0 = 0.f, s1 = 0.f, s2 = 0.f, s3 = 0.f;
    int b = 0;
#pragma unroll 4
    for (; b + 4 <= NB; b += 4) {
        s0 += g_part[(b + 0) * (KE * DD) + e];
        s1 += g_part[(b + 1) * (KE * DD) + e];
        s2 += g_part[(b + 2) * (KE * DD) + e];
        s3 += g_part[(b + 3) * (KE * DD) + e];
    }
    for (; b < NB; ++b) s0 += g_part[b * (KE * DD) + e];
    g_G[e] = (s0 + s1) + (s2 + s3);
}

// ---------------------------------------------------------------------------
// helpers for the fused kernel
// ---------------------------------------------------------------------------
__device__ __forceinline__ void load_w(float* sW, const float* __restrict__ W, int tx) {
#pragma unroll
    for (int it = 0; it < 16; ++it) {
        int idx = tx + 256 * it;          // 4096 float4 slots
        int r = idx >> 5, q = idx & 31;
        float4 v = __ldg(&reinterpret_cast<const float4*>(W)[idx]);
        *reinterpret_cast<float4*>(&sW[r * SP + q * 4]) = v;
    }
}

// 128x128x128 tile GEMM, float4 fragments (LDS.128), k-step 4.
// acc[i][j] = sum_k A[tr+16i][k] * B[tc+16j][k]
__device__ __forceinline__ void gemm_tile(const float* __restrict__ A, const float* __restrict__ B,
                                          int tr, int tc, float acc[8][8]) {
#pragma unroll
    for (int i = 0; i < 8; i++)
#pragma unroll
        for (int j = 0; j < 8; j++) acc[i][j] = 0.f;
#pragma unroll 1
    for (int k4 = 0; k4 < 32; k4++) {
        float4 a[8], b[8];
#pragma unroll
        for (int i = 0; i < 8; i++)
            a[i] = *reinterpret_cast<const float4*>(&A[(tr + 16 * i) * SP + 4 * k4]);
#pragma unroll
        for (int j = 0; j < 8; j++)
            b[j] = *reinterpret_cast<const float4*>(&B[(tc + 16 * j) * SP + 4 * k4]);
#pragma unroll
        for (int i = 0; i < 8; i++)
#pragma unroll
            for (int j = 0; j < 8; j++) {
                acc[i][j] = fmaf(a[i].x, b[j].x, acc[i][j]);
                acc[i][j] = fmaf(a[i].y, b[j].y, acc[i][j]);
                acc[i][j] = fmaf(a[i].z, b[j].z, acc[i][j]);
                acc[i][j] = fmaf(a[i].w, b[j].w, acc[i][j]);
            }
    }
}

// ---------------------------------------------------------------------------
// fused stage kernel: k = f(t, Y); RK4 update; partial U^T Y_next
// Phase order R -> C -> Z keeps exactly ONE 8x8 accumulator live (no spills).
// mode 0: acc = k;       Y = H + 0.5dt k
// mode 1: acc += 2k;     Y = H + 0.5dt k
// mode 2: acc += 2k;     Y = H + dt k
// mode 3: H += dt/6 (acc + k); Y = H (and write d_out)
// ---------------------------------------------------------------------------
__global__ __launch_bounds__(256, 1) void fused_kernel(
    const float* H, const float* __restrict__ U,
    const float* __restrict__ Wz, const float* __restrict__ bz,
    const float* __restrict__ Wr, const float* __restrict__ br,
    const float* __restrict__ Wc, const float* __restrict__ bc,
    const float* __restrict__ Wt, const float* __restrict__ bt,
    const float* __restrict__ mup,
    float* Hout, int mode, float t) {
    extern __shared__ float smem[];
    float* sW = smem;                 // 128*SP
    float* sY = sW + 128 * SP;        // 128*SP
    float* sRY = sY + 128 * SP;       // 128*SP (r*y, later c+t_mod)
    float* sU = sRY + 128 * SP;       // 128*UP
    float* sG = sU + 128 * UP;        // 16*SP

    const int tx = threadIdx.x;
    const int bid = blockIdx.x;
    const int row0 = bid * 128;

    // ---- tile loads (Y, U, G), then Wr ----
#pragma unroll
    for (int it = 0; it < 16; ++it) {
        int idx = tx + 256 * it;
        int r = idx >> 5, q = idx & 31;
        int n = row0 + r;
        float4 v = make_float4(0.f, 0.f, 0.f, 0.f);
        if (n < NN) v = reinterpret_cast<const float4*>(g_Y)[n * 32 + q];
        *reinterpret_cast<float4*>(&sY[r * SP + q * 4]) = v;
    }
#pragma unroll
    for (int it = 0; it < 8; ++it) {
        int idx = tx + 256 * it;
        int r = idx >> 4, k = idx & 15;
        int n = row0 + r;
        sU[r * UP + k] = (n < NN) ? __ldg(&U[n * KE + k]) : 0.f;
    }
#pragma unroll
    for (int it = 0; it < 8; ++it) {
        int idx = tx + 256 * it;
        int k = idx >> 7, d = idx & 127;
        sG[k * SP + d] = g_G[idx];
    }
    load_w(sW, Wr, tx);
    __syncthreads();

    const int tr = tx & 15;
    const int tc = tx >> 4;

    float acc[8][8];    // the single live accumulator

    // ---- R phase: r = sigmoid(Y Wr^T + br); sRY = r * y ----
    gemm_tile(sY, sW, tr, tc, acc);
#pragma unroll
    for (int j = 0; j < 8; j++) {
        int d = tc + 16 * j;
        float brv = __ldg(&br[d]);
#pragma unroll
        for (int i = 0; i < 8; i++) {
            int r = tr + 16 * i;
            float rv = sigm(acc[i][j] + brv);
            sRY[r * SP + d] = rv * sY[r * SP + d];
        }
    }
    __syncthreads();
    load_w(sW, Wc, tx);
    __syncthreads();

    // ---- C phase: c = tanh((r*y) Wc^T + bc); park c + t_mod into sRY ----
    gemm_tile(sRY, sW, tr, tc, acc);
    __syncthreads();   // all threads done reading sRY before overwrite
#pragma unroll
    for (int j = 0; j < 8; j++) {
        int d = tc + 16 * j;
        float bcv = __ldg(&bc[d]);
        float tmv = tanhf(t * __ldg(&Wt[d]) + __ldg(&bt[d]));
#pragma unroll
        for (int i = 0; i < 8; i++) {
            int r = tr + 16 * i;
            sRY[r * SP + d] = tanhf(acc[i][j] + bcv) + tmv;  // exclusive slot
        }
    }
    __syncthreads();
    load_w(sW, Wz, tx);
    __syncthreads();

    // ---- Z phase: oz = 1 - sigmoid(Y Wz^T + bz) ----
    gemm_tile(sY, sW, tr, tc, acc);
    float mu = __ldg(mup);
#pragma unroll
    for (int j = 0; j < 8; j++) {
        int d = tc + 16 * j;
        float bzv = __ldg(&bz[d]);
#pragma unroll
        for (int i = 0; i < 8; i++) acc[i][j] = 1.0f - sigm(acc[i][j] + bzv);
    }
    __syncthreads();   // all threads done reading sY before overwrite

    // ---- smooth + dh; write k into sY (exclusive per-element ownership) ----
#pragma unroll
    for (int i = 0; i < 8; i++) {
        int r = tr + 16 * i;
        float u[KE];
#pragma unroll
        for (int k = 0; k < KE; k++) u[k] = sU[r * UP + k];
#pragma unroll
        for (int j = 0; j < 8; j++) {
            int d = tc + 16 * j;
            float s = 0.f;
#pragma unroll
            for (int k = 0; k < KE; k++) s = fmaf(u[k], sG[k * SP + d], s);
            float y = sY[r * SP + d];
            float dh = acc[i][j] * (sRY[r * SP + d] - y) - mu * (y - s);
            sY[r * SP + d] = dh;
        }
    }
    __syncthreads();

    // ---- coalesced RK4 epilogue; write Y_next back into sY for partial-G ----
#pragma unroll
    for (int it = 0; it < 16; ++it) {
        int idx = tx + 256 * it;
        int r = idx >> 5, q = idx & 31;
        int n = row0 + r;
        float4 kv = *reinterpret_cast<float4*>(&sY[r * SP + q * 4]);
        float4 yn = make_float4(0.f, 0.f, 0.f, 0.f);
        if (n < NN) {
            int g = n * 32 + q;
            float4 h4 = reinterpret_cast<const float4*>(H)[g];
            if (mode == 0) {
                reinterpret_cast<float4*>(g_acc)[g] = kv;
                yn.x = fmaf(0.05f, kv.x, h4.x); yn.y = fmaf(0.05f, kv.y, h4.y);
                yn.z = fmaf(0.05f, kv.z, h4.z); yn.w = fmaf(0.05f, kv.w, h4.w);
            } else if (mode < 3) {
                float4 a4 = reinterpret_cast<float4*>(g_acc)[g];
                a4.x += 2.f * kv.x; a4.y += 2.f * kv.y;
                a4.z += 2.f * kv.z; a4.w += 2.f * kv.w;
                reinterpret_cast<float4*>(g_acc)[g] = a4;
                float cy = (mode == 1) ? 0.05f : 0.1f;
                yn.x = fmaf(cy, kv.x, h4.x); yn.y = fmaf(cy, kv.y, h4.y);
                yn.z = fmaf(cy, kv.z, h4.z); yn.w = fmaf(cy, kv.w, h4.w);
            } else {
                float4 a4 = reinterpret_cast<float4*>(g_acc)[g];
                const float c6 = DTS / 6.0f;
                yn.x = fmaf(c6, a4.x + kv.x, h4.x);
                yn.y = fmaf(c6, a4.y + kv.y, h4.y);
                yn.z = fmaf(c6, a4.z + kv.z, h4.z);
                yn.w = fmaf(c6, a4.w + kv.w, h4.w);
                reinterpret_cast<float4*>(Hout)[g] = yn;
            }
            reinterpret_cast<float4*>(g_Y)[g] = yn;
        }
        *reinterpret_cast<float4*>(&sY[r * SP + q * 4]) = yn;  // 0 for OOB rows
    }
    __syncthreads();

    // ---- fused partial G for the next stage: part = U_tile^T Y_next ----
    {
        int d = tx & 127, kb = (tx >> 7) * 8;
        float f[8];
#pragma unroll
        for (int k = 0; k < 8; k++) f[k] = 0.f;
        for (int r = 0; r < 128; r++) {
            float yv = sY[r * SP + d];
#pragma unroll
            for (int k = 0; k < 8; k++) f[k] = fmaf(sU[r * UP + kb + k], yv, f[k]);
        }
#pragma unroll
        for (int k = 0; k < 8; k++) g_part[bid * (KE * DD) + (kb + k) * DD + d] = f[k];
    }
}

// ---------------------------------------------------------------------------
extern "C" void kernel_launch(void* const* d_in, const int* in_sizes, int n_in,
                              void* d_out, int out_size) {
    const float* h0 = (const float*)d_in[0];
    const float* U  = (const float*)d_in[1];
    const float* Wz = (const float*)d_in[2];
    const float* bz = (const float*)d_in[3];
    const float* Wr = (const float*)d_in[4];
    const float* br = (const float*)d_in[5];
    const float* Wc = (const float*)d_in[6];
    const float* bc = (const float*)d_in[7];
    const float* Wt = (const float*)d_in[8];
    const float* bt = (const float*)d_in[9];
    const float* mu = (const float*)d_in[10];
    float* H = (float*)d_out;

    const size_t smembytes = (size_t)(3 * 128 * SP + 128 * UP + 16 * SP) * sizeof(float); // ~215 KB
    cudaError_t attr_rc = cudaFuncSetAttribute(
        fused_kernel, cudaFuncAttributeMaxDynamicSharedMemorySize, (int)smembytes);
    (void)attr_rc;

    initcopy_kernel<<<(NN * DD / 4 + 255) / 256, 256>>>(h0, H);
    gpartial0_kernel<<<NB, 256>>>(U);

    for (int i = 0; i < 10; i++) {
        float tb = (float)i * DTS;
        float ts[4] = {tb, tb + 0.05f, tb + 0.05f, tb + 0.1f};
        for (int s = 0; s < 4; s++) {
            greduce_kernel<<<8, 256>>>();
            fused_kernel<<<NB, 256, smembytes>>>(H, U, Wz, bz, Wr, br, Wc, bc, Wt, bt,
                                                 mu, H, s, ts[s]);
        }
    }
}

// round 8
// speedup vs baseline: 1.1805x; 1.0650x over previous
#include <cuda_runtime.h>
#include <math.h>

#define NN 100000
#define DD 128
#define KE 16
#define NB 782            // ceil(NN/128)
#define DTS 0.1f
#define SP 132            // padded row stride (floats); 528B rows, 16B-aligned
#define UP 17             // padded row stride for U tile
#define THR 512

// Scratch state (no allocations allowed)
__device__ float g_Y[NN * DD];          // current RK4 evaluation point
__device__ float g_acc[NN * DD];        // k1 + 2k2 + 2k3 accumulator
__device__ float g_part[NB * KE * DD];  // per-block partial U^T Y
__device__ float g_part2[8 * KE * DD];  // stage-A reduced partials
__device__ float g_G[KE * DD];          // reduced G = U^T Y

__device__ __forceinline__ float sigm(float x) { return 1.0f / (1.0f + __expf(-x)); }

// packed fp32x2 FMA: d = a * b + d (per 32-bit lane)
__device__ __forceinline__ void fma2(unsigned long long& d, unsigned long long a,
                                     unsigned long long b) {
    asm("fma.rn.f32x2 %0, %1, %2, %3;" : "=l"(d) : "l"(a), "l"(b), "l"(d));
}
__device__ __forceinline__ float upadd(unsigned long long v) {
    float lo, hi;
    asm("mov.b64 {%0,%1}, %2;" : "=f"(lo), "=f"(hi) : "l"(v));
    return lo + hi;
}

// ---------------------------------------------------------------------------
__global__ void initcopy_kernel(const float* __restrict__ h0, float* __restrict__ H) {
    int i = blockIdx.x * blockDim.x + threadIdx.x;
    if (i < NN * DD / 4) {
        float4 v = reinterpret_cast<const float4*>(h0)[i];
        reinterpret_cast<float4*>(H)[i] = v;
        reinterpret_cast<float4*>(g_Y)[i] = v;
    }
}

// ---------------------------------------------------------------------------
__global__ void gpartial0_kernel(const float* __restrict__ U) {
    int tx = threadIdx.x, bid = blockIdx.x;
    int d = tx & 127, kb = (tx >> 7) * 8;
    float f[8];
#pragma unroll
    for (int k = 0; k < 8; k++) f[k] = 0.f;
    int row0 = bid * 128;
    int rmax = min(128, NN - row0);
    for (int r = 0; r < rmax; r++) {
        int n = row0 + r;
        float yv = g_Y[n * DD + d];
#pragma unroll
        for (int k = 0; k < 8; k++) f[k] = fmaf(__ldg(&U[n * KE + kb + k]), yv, f[k]);
    }
#pragma unroll
    for (int k = 0; k < 8; k++) g_part[bid * (KE * DD) + (kb + k) * DD + d] = f[k];
}

// ---------------------------------------------------------------------------
// two-stage reduction of g_part -> g_G (deterministic fixed order)
// stage A: 64 blocks: bid&7 selects 256-elem group, bid>>3 selects b-chunk of 98
// ---------------------------------------------------------------------------
__global__ void greduceA_kernel() {
    int e = (blockIdx.x & 7) * 256 + threadIdx.x;
    int bc = blockIdx.x >> 3;
    int b0 = bc * 98, b1 = min(NB, b0 + 98);
    float s0 = 0.f, s1 = 0.f, s2 = 0.f, s3 = 0.f;
    int b = b0;
    for (; b + 4 <= b1; b += 4) {
        s0 += g_part[(b + 0) * (KE * DD) + e];
        s1 += g_part[(b + 1) * (KE * DD) + e];
        s2 += g_part[(b + 2) * (KE * DD) + e];
        s3 += g_part[(b + 3) * (KE * DD) + e];
    }
    for (; b < b1; ++b) s0 += g_part[b * (KE * DD) + e];
    g_part2[bc * (KE * DD) + e] = (s0 + s1) + (s2 + s3);
}

__global__ void greduceB_kernel() {
    int e = blockIdx.x * blockDim.x + threadIdx.x;  // 8 x 256
    float s = 0.f;
#pragma unroll
    for (int c = 0; c < 8; c++) s += g_part2[c * (KE * DD) + e];
    g_G[e] = s;
}

// ---------------------------------------------------------------------------
__device__ __forceinline__ void load_w(float* sW, const float* __restrict__ W, int tx) {
#pragma unroll
    for (int it = 0; it < 8; ++it) {
        int idx = tx + THR * it;          // 4096 float4 slots
        int r = idx >> 5, q = idx & 31;
        float4 v = __ldg(&reinterpret_cast<const float4*>(W)[idx]);
        *reinterpret_cast<float4*>(&sW[r * SP + q * 4]) = v;
    }
}

// 128x128x128 tile GEMM with packed f32x2 FMAs.
// Thread (tr in 0..31, tc in 0..15) owns rows {tr+32i} x cols {tc+16j}.
// Accumulate even/odd k-pairs in packed lanes; horizontal add at the end.
__device__ __forceinline__ void gemm_tile(const float* __restrict__ A,
                                          const float* __restrict__ B,
                                          int tr, int tc, float accf[4][8]) {
    unsigned long long acc[4][8];
#pragma unroll
    for (int i = 0; i < 4; i++)
#pragma unroll
        for (int j = 0; j < 8; j++) acc[i][j] = 0ull;
#pragma unroll 1
    for (int k4 = 0; k4 < 32; k4++) {
        ulonglong2 a2[4];
#pragma unroll
        for (int i = 0; i < 4; i++)
            a2[i] = *reinterpret_cast<const ulonglong2*>(&A[(tr + 32 * i) * SP + 4 * k4]);
#pragma unroll
        for (int jh = 0; jh < 2; jh++) {
            ulonglong2 b2[4];
#pragma unroll
            for (int j = 0; j < 4; j++)
                b2[j] = *reinterpret_cast<const ulonglong2*>(
                    &B[(tc + 16 * (jh * 4 + j)) * SP + 4 * k4]);
#pragma unroll
            for (int i = 0; i < 4; i++)
#pragma unroll
                for (int j = 0; j < 4; j++) {
                    fma2(acc[i][jh * 4 + j], a2[i].x, b2[j].x);
                    fma2(acc[i][jh * 4 + j], a2[i].y, b2[j].y);
                }
        }
    }
#pragma unroll
    for (int i = 0; i < 4; i++)
#pragma unroll
        for (int j = 0; j < 8; j++) accf[i][j] = upadd(acc[i][j]);
}

// ---------------------------------------------------------------------------
// fused stage kernel (512 threads): k = f(t, Y); RK4 update; partial U^T Y_next
// Phase order R -> C -> Z keeps ONE live accumulator set.
// ---------------------------------------------------------------------------
__global__ __launch_bounds__(THR, 1) void fused_kernel(
    const float* H, const float* __restrict__ U,
    const float* __restrict__ Wz, const float* __restrict__ bz,
    const float* __restrict__ Wr, const float* __restrict__ br,
    const float* __restrict__ Wc, const float* __restrict__ bc,
    const float* __restrict__ Wt, const float* __restrict__ bt,
    const float* __restrict__ mup,
    float* Hout, int mode, float t) {
    extern __shared__ float smem[];
    float* sW = smem;                 // 128*SP
    float* sY = sW + 128 * SP;        // 128*SP
    float* sRY = sY + 128 * SP;       // 128*SP (r*y, later c+t_mod)
    float* sU = sRY + 128 * SP;       // 128*UP
    float* sG = sU + 128 * UP;        // 16*SP

    const int tx = threadIdx.x;
    const int bid = blockIdx.x;
    const int row0 = bid * 128;

    // ---- tile loads (Y, U, G), then Wr ----
#pragma unroll
    for (int it = 0; it < 8; ++it) {
        int idx = tx + THR * it;
        int r = idx >> 5, q = idx & 31;
        int n = row0 + r;
        float4 v = make_float4(0.f, 0.f, 0.f, 0.f);
        if (n < NN) v = reinterpret_cast<const float4*>(g_Y)[n * 32 + q];
        *reinterpret_cast<float4*>(&sY[r * SP + q * 4]) = v;
    }
#pragma unroll
    for (int it = 0; it < 4; ++it) {
        int idx = tx + THR * it;
        int r = idx >> 4, k = idx & 15;
        int n = row0 + r;
        sU[r * UP + k] = (n < NN) ? __ldg(&U[n * KE + k]) : 0.f;
    }
#pragma unroll
    for (int it = 0; it < 4; ++it) {
        int idx = tx + THR * it;
        int k = idx >> 7, d = idx & 127;
        sG[k * SP + d] = g_G[idx];
    }
    load_w(sW, Wr, tx);
    __syncthreads();

    const int tr = tx & 31;
    const int tc = tx >> 5;

    float acc[4][8];

    // ---- R phase: r = sigmoid(Y Wr^T + br); sRY = r * y ----
    gemm_tile(sY, sW, tr, tc, acc);
#pragma unroll
    for (int j = 0; j < 8; j++) {
        int d = tc + 16 * j;
        float brv = __ldg(&br[d]);
#pragma unroll
        for (int i = 0; i < 4; i++) {
            int r = tr + 32 * i;
            float rv = sigm(acc[i][j] + brv);
            sRY[r * SP + d] = rv * sY[r * SP + d];
        }
    }
    __syncthreads();
    load_w(sW, Wc, tx);
    __syncthreads();

    // ---- C phase: c = tanh((r*y) Wc^T + bc); park c + t_mod into sRY ----
    gemm_tile(sRY, sW, tr, tc, acc);
    __syncthreads();   // all threads done reading sRY before overwrite
#pragma unroll
    for (int j = 0; j < 8; j++) {
        int d = tc + 16 * j;
        float bcv = __ldg(&bc[d]);
        float tmv = tanhf(t * __ldg(&Wt[d]) + __ldg(&bt[d]));
#pragma unroll
        for (int i = 0; i < 4; i++) {
            int r = tr + 32 * i;
            sRY[r * SP + d] = tanhf(acc[i][j] + bcv) + tmv;  // exclusive slot
        }
    }
    __syncthreads();
    load_w(sW, Wz, tx);
    __syncthreads();

    // ---- Z phase: oz = 1 - sigmoid(Y Wz^T + bz) ----
    gemm_tile(sY, sW, tr, tc, acc);
    float mu = __ldg(mup);
#pragma unroll
    for (int j = 0; j < 8; j++) {
        int d = tc + 16 * j;
        float bzv = __ldg(&bz[d]);
#pragma unroll
        for (int i = 0; i < 4; i++) acc[i][j] = 1.0f - sigm(acc[i][j] + bzv);
    }
    __syncthreads();   // all threads done reading sY before overwrite

    // ---- smooth + dh; write k into sY (exclusive per-element ownership) ----
#pragma unroll
    for (int i = 0; i < 4; i++) {
        int r = tr + 32 * i;
        float u[KE];
#pragma unroll
        for (int k = 0; k < KE; k++) u[k] = sU[r * UP + k];
#pragma unroll
        for (int j = 0; j < 8; j++) {
            int d = tc + 16 * j;
            float s = 0.f;
#pragma unroll
            for (int k = 0; k < KE; k++) s = fmaf(u[k], sG[k * SP + d], s);
            float y = sY[r * SP + d];
            float dh = acc[i][j] * (sRY[r * SP + d] - y) - mu * (y - s);
            sY[r * SP + d] = dh;
        }
    }
    __syncthreads();

    // ---- coalesced RK4 epilogue; write Y_next back into sY for partial-G ----
#pragma unroll
    for (int it = 0; it < 8; ++it) {
        int idx = tx + THR * it;
        int r = idx >> 5, q = idx & 31;
        int n = row0 + r;
        float4 kv = *reinterpret_cast<float4*>(&sY[r * SP + q * 4]);
        float4 yn = make_float4(0.f, 0.f, 0.f, 0.f);
        if (n < NN) {
            int g = n * 32 + q;
            float4 h4 = reinterpret_cast<const float4*>(H)[g];
            if (mode == 0) {
                reinterpret_cast<float4*>(g_acc)[g] = kv;
                yn.x = fmaf(0.05f, kv.x, h4.x); yn.y = fmaf(0.05f, kv.y, h4.y);
                yn.z = fmaf(0.05f, kv.z, h4.z); yn.w = fmaf(0.05f, kv.w, h4.w);
            } else if (mode < 3) {
                float4 a4 = reinterpret_cast<float4*>(g_acc)[g];
                a4.x += 2.f * kv.x; a4.y += 2.f * kv.y;
                a4.z += 2.f * kv.z; a4.w += 2.f * kv.w;
                reinterpret_cast<float4*>(g_acc)[g] = a4;
                float cy = (mode == 1) ? 0.05f : 0.1f;
                yn.x = fmaf(cy, kv.x, h4.x); yn.y = fmaf(cy, kv.y, h4.y);
                yn.z = fmaf(cy, kv.z, h4.z); yn.w = fmaf(cy, kv.w, h4.w);
            } else {
                float4 a4 = reinterpret_cast<float4*>(g_acc)[g];
                const float c6 = DTS / 6.0f;
                yn.x = fmaf(c6, a4.x + kv.x, h4.x);
                yn.y = fmaf(c6, a4.y + kv.y, h4.y);
                yn.z = fmaf(c6, a4.z + kv.z, h4.z);
                yn.w = fmaf(c6, a4.w + kv.w, h4.w);
                reinterpret_cast<float4*>(Hout)[g] = yn;
            }
            reinterpret_cast<float4*>(g_Y)[g] = yn;
        }
        *reinterpret_cast<float4*>(&sY[r * SP + q * 4]) = yn;  // 0 for OOB rows
    }
    __syncthreads();

    // ---- fused partial G for the next stage: part = U_tile^T Y_next ----
    {
        int d = tx & 127, kb = (tx >> 7) * 4;   // 4 k-groups of 4
        float f[4];
#pragma unroll
        for (int k = 0; k < 4; k++) f[k] = 0.f;
        for (int r = 0; r < 128; r++) {
            float yv = sY[r * SP + d];
#pragma unroll
            for (int k = 0; k < 4; k++) f[k] = fmaf(sU[r * UP + kb + k], yv, f[k]);
        }
#pragma unroll
        for (int k = 0; k < 4; k++) g_part[bid * (KE * DD) + (kb + k) * DD + d] = f[k];
    }
}

// ---------------------------------------------------------------------------
extern "C" void kernel_launch(void* const* d_in, const int* in_sizes, int n_in,
                              void* d_out, int out_size) {
    const float* h0 = (const float*)d_in[0];
    const float* U  = (const float*)d_in[1];
    const float* Wz = (const float*)d_in[2];
    const float* bz = (const float*)d_in[3];
    const float* Wr = (const float*)d_in[4];
    const float* br = (const float*)d_in[5];
    const float* Wc = (const float*)d_in[6];
    const float* bc = (const float*)d_in[7];
    const float* Wt = (const float*)d_in[8];
    const float* bt = (const float*)d_in[9];
    const float* mu = (const float*)d_in[10];
    float* H = (float*)d_out;

    const size_t smembytes = (size_t)(3 * 128 * SP + 128 * UP + 16 * SP) * sizeof(float); // ~215 KB
    cudaError_t attr_rc = cudaFuncSetAttribute(
        fused_kernel, cudaFuncAttributeMaxDynamicSharedMemorySize, (int)smembytes);
    (void)attr_rc;

    initcopy_kernel<<<(NN * DD / 4 + 255) / 256, 256>>>(h0, H);
    gpartial0_kernel<<<NB, 256>>>(U);

    for (int i = 0; i < 10; i++) {
        float tb = (float)i * DTS;
        float ts[4] = {tb, tb + 0.05f, tb + 0.05f, tb + 0.1f};
        for (int s = 0; s < 4; s++) {
            greduceA_kernel<<<64, 256>>>();
            greduceB_kernel<<<8, 256>>>();
            fused_kernel<<<NB, THR, smembytes>>>(H, U, Wz, bz, Wr, br, Wc, bc, Wt, bt,
                                                 mu, H, s, ts[s]);
        }
    }
}

// round 12
// speedup vs baseline: 2.0840x; 1.7653x over previous
#include <cuda_runtime.h>
#include <cuda_bf16.h>
#include <math.h>
#include <stdint.h>

#define NN 100000
#define DD 128
#define KE 16
#define NB 782            // ceil(NN/128)
#define DTS 0.1f
#define SP 132            // fp32 row stride (floats)
#define UP 17
#define SA 136            // bf16 row stride for MMA tiles (272 B, LDSM conflict-free)
#define THR 512

// Hang-safety audit: no spin-waits/mbarriers anywhere; every __syncthreads()
// below is reached unconditionally by all THR threads (no data-dependent
// control flow precedes any barrier). Graph contains only kernel launches.

// ---------------- global scratch (no allocations allowed) ----------------
__device__ float g_Y[NN * DD];
__device__ float g_acc[NN * DD];
__device__ float g_part[NB * KE * DD];
__device__ float g_part2[8 * KE * DD];
__device__ float g_G[KE * DD];
// bf16 hi/lo weight images, row-major [d][k]: [0]=Wr, [1]=Wz, [2]=Wc
__device__ __align__(16) __nv_bfloat16 g_Wh[3][DD * DD];
__device__ __align__(16) __nv_bfloat16 g_Wl[3][DD * DD];

// ---------------- smem byte offsets ----------------
#define OFF_AHI 0
#define OFF_ALO 34816
#define OFF_WHI 69632
#define OFF_WLO 104448
#define OFF_SY  139264
#define OFF_SU  206848
#define OFF_SG  215552
#define SMEM_BYTES 224000

__device__ __forceinline__ float sigm(float x) { return 1.0f / (1.0f + __expf(-x)); }
__device__ __forceinline__ float bfhi(float a) {
    return __bfloat162float(__float2bfloat16(a));
}
__device__ __forceinline__ unsigned pack2(float a, float b) {
    __nv_bfloat162 t = __floats2bfloat162_rn(a, b);
    return *reinterpret_cast<unsigned*>(&t);
}
__device__ __forceinline__ uint32_t smem_u32(const void* p) {
    uint32_t a;
    asm("{ .reg .u64 t; cvta.to.shared.u64 t, %1; cvt.u32.u64 %0, t; }"
        : "=r"(a) : "l"(p));
    return a;
}
__device__ __forceinline__ void ldsm4(uint32_t a[4], uint32_t addr) {
    asm volatile("ldmatrix.sync.aligned.m8n8.x4.shared.b16 {%0,%1,%2,%3}, [%4];"
                 : "=r"(a[0]), "=r"(a[1]), "=r"(a[2]), "=r"(a[3]) : "r"(addr));
}
__device__ __forceinline__ void ldsm2(uint32_t b[2], uint32_t addr) {
    asm volatile("ldmatrix.sync.aligned.m8n8.x2.shared.b16 {%0,%1}, [%2];"
                 : "=r"(b[0]), "=r"(b[1]) : "r"(addr));
}
__device__ __forceinline__ void mma16816(float c[4], const uint32_t a[4],
                                         const uint32_t b[2]) {
    asm volatile(
        "mma.sync.aligned.m16n8k16.row.col.f32.bf16.bf16.f32 "
        "{%0,%1,%2,%3}, {%4,%5,%6,%7}, {%8,%9}, {%0,%1,%2,%3};"
        : "+f"(c[0]), "+f"(c[1]), "+f"(c[2]), "+f"(c[3])
        : "r"(a[0]), "r"(a[1]), "r"(a[2]), "r"(a[3]), "r"(b[0]), "r"(b[1]));
}

// split-precision 128x128x128 warp GEMM: acc += A*W^T via hi*hi + hi*lo + lo*hi
__device__ __forceinline__ void gemm3(uint32_t aH, uint32_t aL, uint32_t wH,
                                      uint32_t wL, int wm, int wn, int lid,
                                      float acc[2][4][4]) {
    const int arow = lid & 15;
    const int akoff = (lid >> 4) << 3;
    const int brow = lid & 7;
    const int bkoff = ((lid >> 3) & 1) << 3;
#pragma unroll 1
    for (int ks = 0; ks < 8; ks++) {
        const int kb = ks * 16;
        uint32_t Ah[2][4], Al[2][4];
#pragma unroll
        for (int mi = 0; mi < 2; mi++) {
            uint32_t off = (uint32_t)(((wm + mi * 16 + arow) * SA + kb + akoff) * 2);
            ldsm4(Ah[mi], aH + off);
            ldsm4(Al[mi], aL + off);
        }
#pragma unroll
        for (int nj = 0; nj < 4; nj++) {
            uint32_t boff = (uint32_t)(((wn + nj * 8 + brow) * SA + kb + bkoff) * 2);
            uint32_t Bh[2], Bl[2];
            ldsm2(Bh, wH + boff);
            ldsm2(Bl, wL + boff);
#pragma unroll
            for (int mi = 0; mi < 2; mi++) {
                mma16816(acc[mi][nj], Ah[mi], Bh);
                mma16816(acc[mi][nj], Ah[mi], Bl);
                mma16816(acc[mi][nj], Al[mi], Bh);
            }
        }
    }
}

// stage weight image w (0=Wr, 1=Wz, 2=Wc) into smem hi/lo tiles
__device__ __forceinline__ void stage_w(char* wHi, char* wLo, int w, int tx) {
    const float4* sh = reinterpret_cast<const float4*>(g_Wh[w]);
    const float4* sl = reinterpret_cast<const float4*>(g_Wl[w]);
#pragma unroll
    for (int it = 0; it < 4; it++) {
        int i = tx + THR * it;
        int r = i >> 4, sg = i & 15;
        *reinterpret_cast<float4*>(wHi + (r * SA + sg * 8) * 2) = sh[i];
        *reinterpret_cast<float4*>(wLo + (r * SA + sg * 8) * 2) = sl[i];
    }
}

// ---------------------------------------------------------------------------
__global__ void initcopy_kernel(const float* __restrict__ h0, float* __restrict__ H) {
    int i = blockIdx.x * blockDim.x + threadIdx.x;
    if (i < NN * DD / 4) {
        float4 v = reinterpret_cast<const float4*>(h0)[i];
        reinterpret_cast<float4*>(H)[i] = v;
        reinterpret_cast<float4*>(g_Y)[i] = v;
    }
}

__global__ void wprep_kernel(const float* __restrict__ Wr, const float* __restrict__ Wz,
                             const float* __restrict__ Wc) {
    int idx = blockIdx.x * blockDim.x + threadIdx.x;
    if (idx >= 3 * DD * DD) return;
    int w = idx >> 14, e = idx & 16383;
    const float* W = (w == 0) ? Wr : ((w == 1) ? Wz : Wc);
    float v = W[e];
    __nv_bfloat16 hb = __float2bfloat16(v);
    g_Wh[w][e] = hb;
    g_Wl[w][e] = __float2bfloat16(v - __bfloat162float(hb));
}

__global__ void gpartial0_kernel(const float* __restrict__ U) {
    int tx = threadIdx.x, bid = blockIdx.x;
    int d = tx & 127, kb = (tx >> 7) * 8;
    float f[8];
#pragma unroll
    for (int k = 0; k < 8; k++) f[k] = 0.f;
    int row0 = bid * 128;
    int rmax = min(128, NN - row0);
    for (int r = 0; r < rmax; r++) {
        int n = row0 + r;
        float yv = g_Y[n * DD + d];
#pragma unroll
        for (int k = 0; k < 8; k++) f[k] = fmaf(__ldg(&U[n * KE + kb + k]), yv, f[k]);
    }
#pragma unroll
    for (int k = 0; k < 8; k++) g_part[bid * (KE * DD) + (kb + k) * DD + d] = f[k];
}

__global__ void greduceA_kernel() {
    int e = (blockIdx.x & 7) * 256 + threadIdx.x;
    int bc = blockIdx.x >> 3;
    int b0 = bc * 98, b1 = min(NB, b0 + 98);
    float s0 = 0.f, s1 = 0.f, s2 = 0.f, s3 = 0.f;
    int b = b0;
    for (; b + 4 <= b1; b += 4) {
        s0 += g_part[(b + 0) * (KE * DD) + e];
        s1 += g_part[(b + 1) * (KE * DD) + e];
        s2 += g_part[(b + 2) * (KE * DD) + e];
        s3 += g_part[(b + 3) * (KE * DD) + e];
    }
    for (; b < b1; ++b) s0 += g_part[b * (KE * DD) + e];
    g_part2[bc * (KE * DD) + e] = (s0 + s1) + (s2 + s3);
}

__global__ void greduceB_kernel() {
    int e = blockIdx.x * blockDim.x + threadIdx.x;
    float s = 0.f;
#pragma unroll
    for (int c = 0; c < 8; c++) s += g_part2[c * (KE * DD) + e];
    g_G[e] = s;
}

// ---------------------------------------------------------------------------
// fused stage kernel: mma.sync bf16x3 GEMMs + gates + RK4 + partial-G
// ---------------------------------------------------------------------------
__global__ __launch_bounds__(THR, 1) void fused_kernel(
    const float* H, const float* __restrict__ U,
    const float* __restrict__ bz, const float* __restrict__ br,
    const float* __restrict__ bc, const float* __restrict__ Wt,
    const float* __restrict__ bt, const float* __restrict__ mup,
    float* Hout, int mode, float t) {
    extern __shared__ char sb[];
    char* aHi = sb + OFF_AHI;
    char* aLo = sb + OFF_ALO;
    char* wHi = sb + OFF_WHI;
    char* wLo = sb + OFF_WLO;
    float* sY = (float*)(sb + OFF_SY);
    float* sU = (float*)(sb + OFF_SU);
    float* sG = (float*)(sb + OFF_SG);
    const uint32_t baseU = smem_u32(sb);
    const uint32_t aHiU = baseU + OFF_AHI, aLoU = baseU + OFF_ALO;
    const uint32_t wHiU = baseU + OFF_WHI, wLoU = baseU + OFF_WLO;

    const int tx = threadIdx.x;
    const int w = tx >> 5, lid = tx & 31;
    const int wm = (w >> 2) * 32, wn = (w & 3) * 32;
    const int bid = blockIdx.x, row0 = bid * 128;

    // ---- load Y -> sY fp32 + aHi/aLo bf16; sU; sG; Wz images ----
#pragma unroll
    for (int it = 0; it < 8; ++it) {
        int idx = tx + THR * it;
        int r = idx >> 5, q = idx & 31;
        int n = row0 + r;
        float4 v = make_float4(0.f, 0.f, 0.f, 0.f);
        if (n < NN) v = reinterpret_cast<const float4*>(g_Y)[n * 32 + q];
        *reinterpret_cast<float4*>(&sY[r * SP + q * 4]) = v;
        char* p = aHi + (r * SA + q * 4) * 2;
        char* pl = aLo + (r * SA + q * 4) * 2;
        *reinterpret_cast<unsigned*>(p) = pack2(v.x, v.y);
        *reinterpret_cast<unsigned*>(p + 4) = pack2(v.z, v.w);
        *reinterpret_cast<unsigned*>(pl) = pack2(v.x - bfhi(v.x), v.y - bfhi(v.y));
        *reinterpret_cast<unsigned*>(pl + 4) = pack2(v.z - bfhi(v.z), v.w - bfhi(v.w));
    }
#pragma unroll
    for (int it = 0; it < 4; ++it) {
        int idx = tx + THR * it;
        int r = idx >> 4, k = idx & 15;
        int n = row0 + r;
        sU[r * UP + k] = (n < NN) ? __ldg(&U[n * KE + k]) : 0.f;
    }
#pragma unroll
    for (int it = 0; it < 4; ++it) {
        int idx = tx + THR * it;
        int k = idx >> 7, d = idx & 127;
        sG[k * SP + d] = g_G[idx];
    }
    stage_w(wHi, wLo, 1, tx);   // Wz
    __syncthreads();

    // ---- GEMM Z: az = Y * Wz^T -> oz = 1 - sigm(. + bz) ----
    float az[2][4][4];
#pragma unroll
    for (int mi = 0; mi < 2; mi++)
#pragma unroll
        for (int nj = 0; nj < 4; nj++)
#pragma unroll
            for (int c = 0; c < 4; c++) az[mi][nj][c] = 0.f;
    gemm3(aHiU, aLoU, wHiU, wLoU, wm, wn, lid, az);
#pragma unroll
    for (int mi = 0; mi < 2; mi++)
#pragma unroll
        for (int nj = 0; nj < 4; nj++) {
            int c0 = wn + nj * 8 + (lid & 3) * 2;
#pragma unroll
            for (int hh = 0; hh < 2; hh++)
#pragma unroll
                for (int p = 0; p < 2; p++)
                    az[mi][nj][hh * 2 + p] =
                        1.0f - sigm(az[mi][nj][hh * 2 + p] + __ldg(&bz[c0 + p]));
        }
    __syncthreads();
    stage_w(wHi, wLo, 0, tx);   // Wr
    __syncthreads();

    // ---- GEMM R: ar = Y * Wr^T -> rY = sigm(. + br) * y ----
    float ar[2][4][4];
#pragma unroll
    for (int mi = 0; mi < 2; mi++)
#pragma unroll
        for (int nj = 0; nj < 4; nj++)
#pragma unroll
            for (int c = 0; c < 4; c++) ar[mi][nj][c] = 0.f;
    gemm3(aHiU, aLoU, wHiU, wLoU, wm, wn, lid, ar);
#pragma unroll
    for (int mi = 0; mi < 2; mi++)
#pragma unroll
        for (int nj = 0; nj < 4; nj++) {
            int c0 = wn + nj * 8 + (lid & 3) * 2;
#pragma unroll
            for (int hh = 0; hh < 2; hh++) {
                int row = wm + mi * 16 + (lid >> 2) + hh * 8;
#pragma unroll
                for (int p = 0; p < 2; p++) {
                    float rv = sigm(ar[mi][nj][hh * 2 + p] + __ldg(&br[c0 + p]));
                    ar[mi][nj][hh * 2 + p] = rv * sY[row * SP + c0 + p];
                }
            }
        }
    __syncthreads();  // all warps done reading A (Y) and Wr

    // ---- write rY over A tiles; stage Wc ----
#pragma unroll
    for (int mi = 0; mi < 2; mi++)
#pragma unroll
        for (int hh = 0; hh < 2; hh++) {
            int row = wm + mi * 16 + (lid >> 2) + hh * 8;
#pragma unroll
            for (int nj = 0; nj < 4; nj++) {
                int c0 = wn + nj * 8 + (lid & 3) * 2;
                float v0 = ar[mi][nj][hh * 2], v1 = ar[mi][nj][hh * 2 + 1];
                *reinterpret_cast<unsigned*>(aHi + (row * SA + c0) * 2) = pack2(v0, v1);
                *reinterpret_cast<unsigned*>(aLo + (row * SA + c0) * 2) =
                    pack2(v0 - bfhi(v0), v1 - bfhi(v1));
            }
        }
    stage_w(wHi, wLo, 2, tx);   // Wc
    __syncthreads();

    // ---- GEMM C: ac = rY * Wc^T ----
    float ac[2][4][4];
#pragma unroll
    for (int mi = 0; mi < 2; mi++)
#pragma unroll
        for (int nj = 0; nj < 4; nj++)
#pragma unroll
            for (int c = 0; c < 4; c++) ac[mi][nj][c] = 0.f;
    gemm3(aHiU, aLoU, wHiU, wLoU, wm, wn, lid, ac);

    // ---- gating + spectral + dh -> sY (exclusive fragment ownership) ----
    {
        float mu = __ldg(mup);
#pragma unroll
        for (int mi = 0; mi < 2; mi++)
#pragma unroll
            for (int hh = 0; hh < 2; hh++) {
                int row = wm + mi * 16 + (lid >> 2) + hh * 8;
                float u[KE];
#pragma unroll
                for (int k = 0; k < KE; k++) u[k] = sU[row * UP + k];
#pragma unroll
                for (int nj = 0; nj < 4; nj++) {
                    int c0 = wn + nj * 8 + (lid & 3) * 2;
#pragma unroll
                    for (int p = 0; p < 2; p++) {
                        int d = c0 + p;
                        float y = sY[row * SP + d];
                        float s = 0.f;
#pragma unroll
                        for (int k = 0; k < KE; k++)
                            s = fmaf(u[k], sG[k * SP + d], s);
                        float tmv = tanhf(t * __ldg(&Wt[d]) + __ldg(&bt[d]));
                        float cq = tanhf(ac[mi][nj][hh * 2 + p] + __ldg(&bc[d]));
                        float ozv = az[mi][nj][hh * 2 + p];
                        sY[row * SP + d] = ozv * (cq + tmv - y) - mu * (y - s);
                    }
                }
            }
    }
    __syncthreads();

    // ---- coalesced RK4 epilogue; Y_next back into sY for partial-G ----
#pragma unroll
    for (int it = 0; it < 8; ++it) {
        int idx = tx + THR * it;
        int r = idx >> 5, q = idx & 31;
        int n = row0 + r;
        float4 kv = *reinterpret_cast<float4*>(&sY[r * SP + q * 4]);
        float4 yn = make_float4(0.f, 0.f, 0.f, 0.f);
        if (n < NN) {
            int g = n * 32 + q;
            float4 h4 = reinterpret_cast<const float4*>(H)[g];
            if (mode == 0) {
                reinterpret_cast<float4*>(g_acc)[g] = kv;
                yn.x = fmaf(0.05f, kv.x, h4.x); yn.y = fmaf(0.05f, kv.y, h4.y);
                yn.z = fmaf(0.05f, kv.z, h4.z); yn.w = fmaf(0.05f, kv.w, h4.w);
            } else if (mode < 3) {
                float4 a4 = reinterpret_cast<float4*>(g_acc)[g];
                a4.x += 2.f * kv.x; a4.y += 2.f * kv.y;
                a4.z += 2.f * kv.z; a4.w += 2.f * kv.w;
                reinterpret_cast<float4*>(g_acc)[g] = a4;
                float cy = (mode == 1) ? 0.05f : 0.1f;
                yn.x = fmaf(cy, kv.x, h4.x); yn.y = fmaf(cy, kv.y, h4.y);
                yn.z = fmaf(cy, kv.z, h4.z); yn.w = fmaf(cy, kv.w, h4.w);
            } else {
                float4 a4 = reinterpret_cast<float4*>(g_acc)[g];
                const float c6 = DTS / 6.0f;
                yn.x = fmaf(c6, a4.x + kv.x, h4.x);
                yn.y = fmaf(c6, a4.y + kv.y, h4.y);
                yn.z = fmaf(c6, a4.z + kv.z, h4.z);
                yn.w = fmaf(c6, a4.w + kv.w, h4.w);
                reinterpret_cast<float4*>(Hout)[g] = yn;
            }
            reinterpret_cast<float4*>(g_Y)[g] = yn;
        }
        *reinterpret_cast<float4*>(&sY[r * SP + q * 4]) = yn;
    }
    __syncthreads();

    // ---- fused partial G for next stage ----
    {
        int d = tx & 127, kb = (tx >> 7) * 4;
        float f[4];
#pragma unroll
        for (int k = 0; k < 4; k++) f[k] = 0.f;
        for (int r = 0; r < 128; r++) {
            float yv = sY[r * SP + d];
#pragma unroll
            for (int k = 0; k < 4; k++) f[k] = fmaf(sU[r * UP + kb + k], yv, f[k]);
        }
#pragma unroll
        for (int k = 0; k < 4; k++) g_part[bid * (KE * DD) + (kb + k) * DD + d] = f[k];
    }
}

// ---------------------------------------------------------------------------
extern "C" void kernel_launch(void* const* d_in, const int* in_sizes, int n_in,
                              void* d_out, int out_size) {
    const float* h0 = (const float*)d_in[0];
    const float* U  = (const float*)d_in[1];
    const float* Wz = (const float*)d_in[2];
    const float* bz = (const float*)d_in[3];
    const float* Wr = (const float*)d_in[4];
    const float* br = (const float*)d_in[5];
    const float* Wc = (const float*)d_in[6];
    const float* bc = (const float*)d_in[7];
    const float* Wt = (const float*)d_in[8];
    const float* bt = (const float*)d_in[9];
    const float* mu = (const float*)d_in[10];
    float* H = (float*)d_out;

    cudaError_t rc = cudaFuncSetAttribute(
        fused_kernel, cudaFuncAttributeMaxDynamicSharedMemorySize, SMEM_BYTES);
    (void)rc;

    initcopy_kernel<<<(NN * DD / 4 + 255) / 256, 256>>>(h0, H);
    wprep_kernel<<<(3 * DD * DD + 511) / 512, 512>>>(Wr, Wz, Wc);
    gpartial0_kernel<<<NB, 256>>>(U);

    for (int i = 0; i < 10; i++) {
        float tb = (float)i * DTS;
        float ts[4] = {tb, tb + 0.05f, tb + 0.05f, tb + 0.1f};
        for (int s = 0; s < 4; s++) {
            greduceA_kernel<<<64, 256>>>();
            greduceB_kernel<<<8, 256>>>();
            fused_kernel<<<NB, THR, SMEM_BYTES>>>(H, U, bz, br, bc, Wt, bt, mu,
                                                  H, s, ts[s]);
        }
    }
}

// round 13
// speedup vs baseline: 2.3987x; 1.1510x over previous
#include <cuda_runtime.h>
#include <cuda_bf16.h>
#include <math.h>
#include <stdint.h>

#define NN 100000
#define DD 128
#define KE 16
#define NB 782            // ceil(NN/128)
#define DTS 0.1f
#define SP 132            // fp32 row stride (floats)
#define UP 20             // U row stride (floats): kb offsets stay 16B-aligned
#define SA 136            // bf16 row stride for MMA tiles (272 B, LDSM conflict-free)
#define THR 512

// ---------------- global scratch (no allocations allowed) ----------------
__device__ float g_Y[NN * DD];
__device__ float g_acc[NN * DD];
__device__ float g_part[NB * KE * DD];
__device__ float g_part2[8 * KE * DD];
__device__ float g_G[KE * DD];
__device__ float g_tmod[DD];            // tanh(t*Wt + bt), per stage
// bf16 hi/lo weight images, row-major [d][k]: [0]=Wr, [1]=Wz, [2]=Wc
__device__ __align__(16) __nv_bfloat16 g_Wh[3][DD * DD];
__device__ __align__(16) __nv_bfloat16 g_Wl[3][DD * DD];

// ---------------- smem byte offsets ----------------
#define OFF_AHI 0
#define OFF_ALO 34816
#define OFF_WHI 69632
#define OFF_WLO 104448
#define OFF_SY  139264
#define OFF_SU  206848     // 128*20*4 = 10240
#define OFF_SG  217088     // 16*132*4 = 8448
#define SMEM_BYTES 225536

// fast transcendentals via MUFU path (err ~1e-6; tolerance margin ~1000x)
__device__ __forceinline__ float sigm(float x) {
    return __fdividef(1.0f, 1.0f + __expf(-x));
}
__device__ __forceinline__ float tanh_fast(float x) {
    float e = __expf(2.0f * x);
    return 1.0f - __fdividef(2.0f, e + 1.0f);   // +/-inf-safe: ->1 / ->-1
}
__device__ __forceinline__ float bfhi(float a) {
    return __bfloat162float(__float2bfloat16(a));
}
__device__ __forceinline__ unsigned pack2(float a, float b) {
    __nv_bfloat162 t = __floats2bfloat162_rn(a, b);
    return *reinterpret_cast<unsigned*>(&t);
}
__device__ __forceinline__ uint32_t smem_u32(const void* p) {
    uint32_t a;
    asm("{ .reg .u64 t; cvta.to.shared.u64 t, %1; cvt.u32.u64 %0, t; }"
        : "=r"(a) : "l"(p));
    return a;
}
__device__ __forceinline__ void ldsm4(uint32_t a[4], uint32_t addr) {
    asm volatile("ldmatrix.sync.aligned.m8n8.x4.shared.b16 {%0,%1,%2,%3}, [%4];"
                 : "=r"(a[0]), "=r"(a[1]), "=r"(a[2]), "=r"(a[3]) : "r"(addr));
}
__device__ __forceinline__ void ldsm2(uint32_t b[2], uint32_t addr) {
    asm volatile("ldmatrix.sync.aligned.m8n8.x2.shared.b16 {%0,%1}, [%2];"
                 : "=r"(b[0]), "=r"(b[1]) : "r"(addr));
}
__device__ __forceinline__ void mma16816(float c[4], const uint32_t a[4],
                                         const uint32_t b[2]) {
    asm volatile(
        "mma.sync.aligned.m16n8k16.row.col.f32.bf16.bf16.f32 "
        "{%0,%1,%2,%3}, {%4,%5,%6,%7}, {%8,%9}, {%0,%1,%2,%3};"
        : "+f"(c[0]), "+f"(c[1]), "+f"(c[2]), "+f"(c[3])
        : "r"(a[0]), "r"(a[1]), "r"(a[2]), "r"(a[3]), "r"(b[0]), "r"(b[1]));
}

// split-precision 128x128x128 warp GEMM: acc += A*W^T via hi*hi + hi*lo + lo*hi
__device__ __forceinline__ void gemm3(uint32_t aH, uint32_t aL, uint32_t wH,
                                      uint32_t wL, int wm, int wn, int lid,
                                      float acc[2][4][4]) {
    const int arow = lid & 15;
    const int akoff = (lid >> 4) << 3;
    const int brow = lid & 7;
    const int bkoff = ((lid >> 3) & 1) << 3;
#pragma unroll 1
    for (int ks = 0; ks < 8; ks++) {
        const int kb = ks * 16;
        uint32_t Ah[2][4], Al[2][4];
#pragma unroll
        for (int mi = 0; mi < 2; mi++) {
            uint32_t off = (uint32_t)(((wm + mi * 16 + arow) * SA + kb + akoff) * 2);
            ldsm4(Ah[mi], aH + off);
            ldsm4(Al[mi], aL + off);
        }
#pragma unroll
        for (int nj = 0; nj < 4; nj++) {
            uint32_t boff = (uint32_t)(((wn + nj * 8 + brow) * SA + kb + bkoff) * 2);
            uint32_t Bh[2], Bl[2];
            ldsm2(Bh, wH + boff);
            ldsm2(Bl, wL + boff);
#pragma unroll
            for (int mi = 0; mi < 2; mi++) {
                mma16816(acc[mi][nj], Ah[mi], Bh);
                mma16816(acc[mi][nj], Ah[mi], Bl);
                mma16816(acc[mi][nj], Al[mi], Bh);
            }
        }
    }
}

// stage weight image w (0=Wr, 1=Wz, 2=Wc) into smem hi/lo tiles
__device__ __forceinline__ void stage_w(char* wHi, char* wLo, int w, int tx) {
    const float4* sh = reinterpret_cast<const float4*>(g_Wh[w]);
    const float4* sl = reinterpret_cast<const float4*>(g_Wl[w]);
#pragma unroll
    for (int it = 0; it < 4; it++) {
        int i = tx + THR * it;
        int r = i >> 4, sg = i & 15;
        *reinterpret_cast<float4*>(wHi + (r * SA + sg * 8) * 2) = sh[i];
        *reinterpret_cast<float4*>(wLo + (r * SA + sg * 8) * 2) = sl[i];
    }
}

// ---------------------------------------------------------------------------
__global__ void initcopy_kernel(const float* __restrict__ h0, float* __restrict__ H) {
    int i = blockIdx.x * blockDim.x + threadIdx.x;
    if (i < NN * DD / 4) {
        float4 v = reinterpret_cast<const float4*>(h0)[i];
        reinterpret_cast<float4*>(H)[i] = v;
        reinterpret_cast<float4*>(g_Y)[i] = v;
    }
}

__global__ void wprep_kernel(const float* __restrict__ Wr, const float* __restrict__ Wz,
                             const float* __restrict__ Wc) {
    int idx = blockIdx.x * blockDim.x + threadIdx.x;
    if (idx >= 3 * DD * DD) return;
    int w = idx >> 14, e = idx & 16383;
    const float* W = (w == 0) ? Wr : ((w == 1) ? Wz : Wc);
    float v = W[e];
    __nv_bfloat16 hb = __float2bfloat16(v);
    g_Wh[w][e] = hb;
    g_Wl[w][e] = __float2bfloat16(v - __bfloat162float(hb));
}

__global__ void gpartial0_kernel(const float* __restrict__ U) {
    int tx = threadIdx.x, bid = blockIdx.x;
    int d = tx & 127, kb = (tx >> 7) * 8;
    float f[8];
#pragma unroll
    for (int k = 0; k < 8; k++) f[k] = 0.f;
    int row0 = bid * 128;
    int rmax = min(128, NN - row0);
    for (int r = 0; r < rmax; r++) {
        int n = row0 + r;
        float yv = g_Y[n * DD + d];
#pragma unroll
        for (int k = 0; k < 8; k++) f[k] = fmaf(__ldg(&U[n * KE + kb + k]), yv, f[k]);
    }
#pragma unroll
    for (int k = 0; k < 8; k++) g_part[bid * (KE * DD) + (kb + k) * DD + d] = f[k];
}

__global__ void greduceA_kernel() {
    int e = (blockIdx.x & 7) * 256 + threadIdx.x;
    int bc = blockIdx.x >> 3;
    int b0 = bc * 98, b1 = min(NB, b0 + 98);
    float s0 = 0.f, s1 = 0.f, s2 = 0.f, s3 = 0.f;
    int b = b0;
    for (; b + 4 <= b1; b += 4) {
        s0 += g_part[(b + 0) * (KE * DD) + e];
        s1 += g_part[(b + 1) * (KE * DD) + e];
        s2 += g_part[(b + 2) * (KE * DD) + e];
        s3 += g_part[(b + 3) * (KE * DD) + e];
    }
    for (; b < b1; ++b) s0 += g_part[b * (KE * DD) + e];
    g_part2[bc * (KE * DD) + e] = (s0 + s1) + (s2 + s3);
}

// reduce stage B + per-stage t_mod precompute (identical for all blocks)
__global__ void greduceB_kernel(const float* __restrict__ Wt,
                                const float* __restrict__ bt, float t) {
    int e = blockIdx.x * blockDim.x + threadIdx.x;
    float s = 0.f;
#pragma unroll
    for (int c = 0; c < 8; c++) s += g_part2[c * (KE * DD) + e];
    g_G[e] = s;
    if (e < DD) g_tmod[e] = tanh_fast(t * __ldg(&Wt[e]) + __ldg(&bt[e]));
}

// ---------------------------------------------------------------------------
// fused stage kernel: mma.sync bf16x3 GEMMs + gates + RK4 + partial-G
// ---------------------------------------------------------------------------
__global__ __launch_bounds__(THR, 1) void fused_kernel(
    const float* H, const float* __restrict__ U,
    const float* __restrict__ bz, const float* __restrict__ br,
    const float* __restrict__ bc, const float* __restrict__ mup,
    float* Hout, int mode, float t) {
    extern __shared__ char sb[];
    char* aHi = sb + OFF_AHI;
    char* aLo = sb + OFF_ALO;
    char* wHi = sb + OFF_WHI;
    char* wLo = sb + OFF_WLO;
    float* sY = (float*)(sb + OFF_SY);
    float* sU = (float*)(sb + OFF_SU);
    float* sG = (float*)(sb + OFF_SG);
    const uint32_t baseU = smem_u32(sb);
    const uint32_t aHiU = baseU + OFF_AHI, aLoU = baseU + OFF_ALO;
    const uint32_t wHiU = baseU + OFF_WHI, wLoU = baseU + OFF_WLO;

    const int tx = threadIdx.x;
    const int w = tx >> 5, lid = tx & 31;
    const int wm = (w >> 2) * 32, wn = (w & 3) * 32;
    const int bid = blockIdx.x, row0 = bid * 128;

    // ---- load Y -> sY fp32 + aHi/aLo bf16; sU; sG; Wz images ----
#pragma unroll
    for (int it = 0; it < 8; ++it) {
        int idx = tx + THR * it;
        int r = idx >> 5, q = idx & 31;
        int n = row0 + r;
        float4 v = make_float4(0.f, 0.f, 0.f, 0.f);
        if (n < NN) v = reinterpret_cast<const float4*>(g_Y)[n * 32 + q];
        *reinterpret_cast<float4*>(&sY[r * SP + q * 4]) = v;
        char* p = aHi + (r * SA + q * 4) * 2;
        char* pl = aLo + (r * SA + q * 4) * 2;
        *reinterpret_cast<unsigned*>(p) = pack2(v.x, v.y);
        *reinterpret_cast<unsigned*>(p + 4) = pack2(v.z, v.w);
        *reinterpret_cast<unsigned*>(pl) = pack2(v.x - bfhi(v.x), v.y - bfhi(v.y));
        *reinterpret_cast<unsigned*>(pl + 4) = pack2(v.z - bfhi(v.z), v.w - bfhi(v.w));
    }
#pragma unroll
    for (int it = 0; it < 4; ++it) {
        int idx = tx + THR * it;
        int r = idx >> 4, k = idx & 15;
        int n = row0 + r;
        sU[r * UP + k] = (n < NN) ? __ldg(&U[n * KE + k]) : 0.f;
    }
#pragma unroll
    for (int it = 0; it < 4; ++it) {
        int idx = tx + THR * it;
        int k = idx >> 7, d = idx & 127;
        sG[k * SP + d] = g_G[idx];
    }
    stage_w(wHi, wLo, 1, tx);   // Wz
    __syncthreads();

    // ---- GEMM Z: az = Y * Wz^T -> oz = 1 - sigm(. + bz) ----
    float az[2][4][4];
#pragma unroll
    for (int mi = 0; mi < 2; mi++)
#pragma unroll
        for (int nj = 0; nj < 4; nj++)
#pragma unroll
            for (int c = 0; c < 4; c++) az[mi][nj][c] = 0.f;
    gemm3(aHiU, aLoU, wHiU, wLoU, wm, wn, lid, az);
#pragma unroll
    for (int mi = 0; mi < 2; mi++)
#pragma unroll
        for (int nj = 0; nj < 4; nj++) {
            int c0 = wn + nj * 8 + (lid & 3) * 2;
#pragma unroll
            for (int hh = 0; hh < 2; hh++)
#pragma unroll
                for (int p = 0; p < 2; p++)
                    az[mi][nj][hh * 2 + p] =
                        1.0f - sigm(az[mi][nj][hh * 2 + p] + __ldg(&bz[c0 + p]));
        }
    __syncthreads();
    stage_w(wHi, wLo, 0, tx);   // Wr
    __syncthreads();

    // ---- GEMM R: ar = Y * Wr^T -> rY = sigm(. + br) * y ----
    float ar[2][4][4];
#pragma unroll
    for (int mi = 0; mi < 2; mi++)
#pragma unroll
        for (int nj = 0; nj < 4; nj++)
#pragma unroll
            for (int c = 0; c < 4; c++) ar[mi][nj][c] = 0.f;
    gemm3(aHiU, aLoU, wHiU, wLoU, wm, wn, lid, ar);
#pragma unroll
    for (int mi = 0; mi < 2; mi++)
#pragma unroll
        for (int nj = 0; nj < 4; nj++) {
            int c0 = wn + nj * 8 + (lid & 3) * 2;
#pragma unroll
            for (int hh = 0; hh < 2; hh++) {
                int row = wm + mi * 16 + (lid >> 2) + hh * 8;
#pragma unroll
                for (int p = 0; p < 2; p++) {
                    float rv = sigm(ar[mi][nj][hh * 2 + p] + __ldg(&br[c0 + p]));
                    ar[mi][nj][hh * 2 + p] = rv * sY[row * SP + c0 + p];
                }
            }
        }
    __syncthreads();  // all warps done reading A (Y) and Wr

    // ---- write rY over A tiles; stage Wc ----
#pragma unroll
    for (int mi = 0; mi < 2; mi++)
#pragma unroll
        for (int hh = 0; hh < 2; hh++) {
            int row = wm + mi * 16 + (lid >> 2) + hh * 8;
#pragma unroll
            for (int nj = 0; nj < 4; nj++) {
                int c0 = wn + nj * 8 + (lid & 3) * 2;
                float v0 = ar[mi][nj][hh * 2], v1 = ar[mi][nj][hh * 2 + 1];
                *reinterpret_cast<unsigned*>(aHi + (row * SA + c0) * 2) = pack2(v0, v1);
                *reinterpret_cast<unsigned*>(aLo + (row * SA + c0) * 2) =
                    pack2(v0 - bfhi(v0), v1 - bfhi(v1));
            }
        }
    stage_w(wHi, wLo, 2, tx);   // Wc
    __syncthreads();

    // ---- GEMM C: ac = rY * Wc^T ----
    float ac[2][4][4];
#pragma unroll
    for (int mi = 0; mi < 2; mi++)
#pragma unroll
        for (int nj = 0; nj < 4; nj++)
#pragma unroll
            for (int c = 0; c < 4; c++) ac[mi][nj][c] = 0.f;
    gemm3(aHiU, aLoU, wHiU, wLoU, wm, wn, lid, ac);

    // ---- gating + spectral + dh -> sY (exclusive fragment ownership) ----
    {
        float mu = __ldg(mup);
#pragma unroll
        for (int mi = 0; mi < 2; mi++)
#pragma unroll
            for (int hh = 0; hh < 2; hh++) {
                int row = wm + mi * 16 + (lid >> 2) + hh * 8;
                float u[KE];
                {
                    const float4* up = reinterpret_cast<const float4*>(&sU[row * UP]);
#pragma unroll
                    for (int q = 0; q < 4; q++) {
                        float4 uv = up[q];
                        u[q * 4 + 0] = uv.x; u[q * 4 + 1] = uv.y;
                        u[q * 4 + 2] = uv.z; u[q * 4 + 3] = uv.w;
                    }
                }
#pragma unroll
                for (int nj = 0; nj < 4; nj++) {
                    int c0 = wn + nj * 8 + (lid & 3) * 2;
                    float s0 = 0.f, s1 = 0.f;
#pragma unroll
                    for (int k = 0; k < KE; k++) {
                        float2 g = *reinterpret_cast<const float2*>(&sG[k * SP + c0]);
                        s0 = fmaf(u[k], g.x, s0);
                        s1 = fmaf(u[k], g.y, s1);
                    }
#pragma unroll
                    for (int p = 0; p < 2; p++) {
                        int d = c0 + p;
                        float y = sY[row * SP + d];
                        float sv = p ? s1 : s0;
                        float tmv = __ldg(&g_tmod[d]);
                        float cq = tanh_fast(ac[mi][nj][hh * 2 + p] + __ldg(&bc[d]));
                        float ozv = az[mi][nj][hh * 2 + p];
                        sY[row * SP + d] = ozv * (cq + tmv - y) - mu * (y - sv);
                    }
                }
            }
    }
    __syncthreads();

    // ---- coalesced RK4 epilogue; Y_next back into sY for partial-G ----
#pragma unroll
    for (int it = 0; it < 8; ++it) {
        int idx = tx + THR * it;
        int r = idx >> 5, q = idx & 31;
        int n = row0 + r;
        float4 kv = *reinterpret_cast<float4*>(&sY[r * SP + q * 4]);
        float4 yn = make_float4(0.f, 0.f, 0.f, 0.f);
        if (n < NN) {
            int g = n * 32 + q;
            float4 h4 = reinterpret_cast<const float4*>(H)[g];
            if (mode == 0) {
                reinterpret_cast<float4*>(g_acc)[g] = kv;
                yn.x = fmaf(0.05f, kv.x, h4.x); yn.y = fmaf(0.05f, kv.y, h4.y);
                yn.z = fmaf(0.05f, kv.z, h4.z); yn.w = fmaf(0.05f, kv.w, h4.w);
            } else if (mode < 3) {
                float4 a4 = reinterpret_cast<float4*>(g_acc)[g];
                a4.x += 2.f * kv.x; a4.y += 2.f * kv.y;
                a4.z += 2.f * kv.z; a4.w += 2.f * kv.w;
                reinterpret_cast<float4*>(g_acc)[g] = a4;
                float cy = (mode == 1) ? 0.05f : 0.1f;
                yn.x = fmaf(cy, kv.x, h4.x); yn.y = fmaf(cy, kv.y, h4.y);
                yn.z = fmaf(cy, kv.z, h4.z); yn.w = fmaf(cy, kv.w, h4.w);
            } else {
                float4 a4 = reinterpret_cast<float4*>(g_acc)[g];
                const float c6 = DTS / 6.0f;
                yn.x = fmaf(c6, a4.x + kv.x, h4.x);
                yn.y = fmaf(c6, a4.y + kv.y, h4.y);
                yn.z = fmaf(c6, a4.z + kv.z, h4.z);
                yn.w = fmaf(c6, a4.w + kv.w, h4.w);
                reinterpret_cast<float4*>(Hout)[g] = yn;
            }
            reinterpret_cast<float4*>(g_Y)[g] = yn;
        }
        *reinterpret_cast<float4*>(&sY[r * SP + q * 4]) = yn;
    }
    __syncthreads();

    // ---- fused partial G for next stage (broadcast u via LDS.128) ----
    {
        int d = tx & 127, kb = (tx >> 7) * 4;
        float4 f = make_float4(0.f, 0.f, 0.f, 0.f);
#pragma unroll 4
        for (int r = 0; r < 128; r++) {
            float yv = sY[r * SP + d];
            float4 u4 = *reinterpret_cast<const float4*>(&sU[r * UP + kb]);
            f.x = fmaf(u4.x, yv, f.x);
            f.y = fmaf(u4.y, yv, f.y);
            f.z = fmaf(u4.z, yv, f.z);
            f.w = fmaf(u4.w, yv, f.w);
        }
        float* gp = &g_part[bid * (KE * DD)];
        gp[(kb + 0) * DD + d] = f.x;
        gp[(kb + 1) * DD + d] = f.y;
        gp[(kb + 2) * DD + d] = f.z;
        gp[(kb + 3) * DD + d] = f.w;
    }
}

// ---------------------------------------------------------------------------
extern "C" void kernel_launch(void* const* d_in, const int* in_sizes, int n_in,
                              void* d_out, int out_size) {
    const float* h0 = (const float*)d_in[0];
    const float* U  = (const float*)d_in[1];
    const float* Wz = (const float*)d_in[2];
    const float* bz = (const float*)d_in[3];
    const float* Wr = (const float*)d_in[4];
    const float* br = (const float*)d_in[5];
    const float* Wc = (const float*)d_in[6];
    const float* bc = (const float*)d_in[7];
    const float* Wt = (const float*)d_in[8];
    const float* bt = (const float*)d_in[9];
    const float* mu = (const float*)d_in[10];
    float* H = (float*)d_out;

    cudaError_t rc = cudaFuncSetAttribute(
        fused_kernel, cudaFuncAttributeMaxDynamicSharedMemorySize, SMEM_BYTES);
    (void)rc;

    initcopy_kernel<<<(NN * DD / 4 + 255) / 256, 256>>>(h0, H);
    wprep_kernel<<<(3 * DD * DD + 511) / 512, 512>>>(Wr, Wz, Wc);
    gpartial0_kernel<<<NB, 256>>>(U);

    for (int i = 0; i < 10; i++) {
        float tb = (float)i * DTS;
        float ts[4] = {tb, tb + 0.05f, tb + 0.05f, tb + 0.1f};
        for (int s = 0; s < 4; s++) {
            greduceA_kernel<<<64, 256>>>();
            greduceB_kernel<<<8, 256>>>(Wt, bt, ts[s]);
            fused_kernel<<<NB, THR, SMEM_BYTES>>>(H, U, bz, br, bc, mu,
                                                  H, s, ts[s]);
        }
    }
}